// round 2
// baseline (speedup 1.0000x reference)
#include <cuda_runtime.h>
#include <math.h>

#define BATCH 512
#define TFEAT 204
#define NFEAT 20
#define CDIM  256
#define SUBD  40
#define D1K   296   // CDIM + SUBD

// ---------------- scratch (device globals; no runtime allocation) ----------------
__device__ float g_bufA[BATCH * TFEAT * CDIM];
__device__ float g_bufB[BATCH * TFEAT * CDIM];

__device__ float g_fd1t[NFEAT * CDIM];
__device__ float g_c1t[768 * CDIM];
__device__ float g_c2t[768 * CDIM];
__device__ float g_fd2t[CDIM * CDIM];
__device__ float g_d1t[D1K * CDIM];
__device__ float g_d2t[CDIM * CDIM];
__device__ float g_w1i[CDIM * 768];
__device__ float g_w1h[CDIM * 768];
__device__ float g_w2i[CDIM * 768];
__device__ float g_w2h[CDIM * 768];
__device__ float g_w3i[CDIM * 768];
__device__ float g_w3h[CDIM * 768];
__device__ float g_owt[CDIM * SUBD];

// ---------------- transpose: dst[k*N + n] = src[n*K + k] ----------------
__global__ void transpose_k(const float* __restrict__ src, float* __restrict__ dst,
                            int N, int K) {
    int idx = blockIdx.x * 256 + threadIdx.x;
    if (idx < N * K) {
        int n = idx / K;
        int k = idx - n * K;
        dst[k * N + n] = src[idx];
    }
}

// ---------------- fd1: tanh(features @ fd1_w^T + b) -> g_bufA [b,t,c] ----------------
__global__ void fd1_kernel(const float* __restrict__ feat, const float* __restrict__ bias) {
    __shared__ float fs[NFEAT];
    int row = blockIdx.x;            // b*TFEAT + t
    int tid = threadIdx.x;           // c
    if (tid < NFEAT) fs[tid] = feat[row * NFEAT + tid];
    __syncthreads();
    float acc = bias[tid];
#pragma unroll
    for (int k = 0; k < NFEAT; k++)
        acc += g_fd1t[k * CDIM + tid] * fs[k];
    g_bufA[row * CDIM + tid] = tanhf(acc);
}

// ---------------- conv/fc: out[b,t,c] = tanh(bias[c] + sum_{i,j} wt[(i*KW+j)*256+c] * in[b,t+j,i]) ----
// KW=3 -> conv1d valid; KW=1 -> plain dense. in/out layout [b, t, c] contiguous in c.
template <int KW>
__global__ void conv_kernel(const float* __restrict__ in, const float* __restrict__ wt,
                            const float* __restrict__ bias, float* __restrict__ out,
                            int T_in, int T_out) {
    const int TT = 16;
    const int ROWS = TT + KW - 1;
    const int PAD = 258;             // avoid 4-way bank conflicts on row-strided reads
    __shared__ float in_s[ROWS * PAD];

    int b = blockIdx.y;
    int t0 = blockIdx.x * TT;
    int tid = threadIdx.x;

#pragma unroll
    for (int r = 0; r < ROWS; r++) {
        int t = t0 + r;
        in_s[r * PAD + tid] = (t < T_in) ? in[(b * T_in + t) * CDIM + tid] : 0.f;
    }
    __syncthreads();

    int tg = tid & 3;                // 4 t-groups
    int c0 = (tid >> 2) * 4;         // 64 c-groups of 4 channels

    float acc[4][4];
#pragma unroll
    for (int a = 0; a < 4; a++)
#pragma unroll
        for (int c = 0; c < 4; c++) acc[a][c] = 0.f;

#pragma unroll 2
    for (int i = 0; i < CDIM; i++) {
#pragma unroll
        for (int j = 0; j < KW; j++) {
            float4 w = *reinterpret_cast<const float4*>(&wt[(i * KW + j) * CDIM + c0]);
#pragma unroll
            for (int tt = 0; tt < 4; tt++) {
                float xv = in_s[(tg * 4 + tt + j) * PAD + i];
                acc[tt][0] += xv * w.x;
                acc[tt][1] += xv * w.y;
                acc[tt][2] += xv * w.z;
                acc[tt][3] += xv * w.w;
            }
        }
    }

    float4 bv = *reinterpret_cast<const float4*>(&bias[c0]);
#pragma unroll
    for (int tt = 0; tt < 4; tt++) {
        int t = t0 + tg * 4 + tt;
        if (t < T_out) {
            float4 o;
            o.x = tanhf(acc[tt][0] + bv.x);
            o.y = tanhf(acc[tt][1] + bv.y);
            o.z = tanhf(acc[tt][2] + bv.z);
            o.w = tanhf(acc[tt][3] + bv.w);
            *reinterpret_cast<float4*>(&out[(b * T_out + t) * CDIM + c0]) = o;
        }
    }
}

// ---------------- GRU stage: thread j owns h-column j (gates j, 256+j, 512+j) ----------------
__device__ __forceinline__ void gru_stage(const float* __restrict__ xs,  // [k][4] smem
                                          float* __restrict__ hs,        // [k][4] smem
                                          const float* __restrict__ wit, // [k][768] transposed
                                          const float* __restrict__ wht,
                                          const float* __restrict__ bi,
                                          const float* __restrict__ bh,
                                          int j) {
    float ai0[4], ai1[4], ai2[4], ah0[4], ah1[4], ah2[4];
#pragma unroll
    for (int b = 0; b < 4; b++) {
        ai0[b] = 0.f; ai1[b] = 0.f; ai2[b] = 0.f;
        ah0[b] = 0.f; ah1[b] = 0.f; ah2[b] = 0.f;
    }
#pragma unroll 2
    for (int k = 0; k < CDIM; k++) {
        float4 xv = *reinterpret_cast<const float4*>(&xs[k * 4]);
        float4 hv = *reinterpret_cast<const float4*>(&hs[k * 4]);
        const float* wik = &wit[k * 768 + j];
        const float* whk = &wht[k * 768 + j];
        float wi0 = wik[0], wi1 = wik[CDIM], wi2 = wik[2 * CDIM];
        float wh0 = whk[0], wh1 = whk[CDIM], wh2 = whk[2 * CDIM];
        ai0[0] += wi0 * xv.x; ai0[1] += wi0 * xv.y; ai0[2] += wi0 * xv.z; ai0[3] += wi0 * xv.w;
        ai1[0] += wi1 * xv.x; ai1[1] += wi1 * xv.y; ai1[2] += wi1 * xv.z; ai1[3] += wi1 * xv.w;
        ai2[0] += wi2 * xv.x; ai2[1] += wi2 * xv.y; ai2[2] += wi2 * xv.z; ai2[3] += wi2 * xv.w;
        ah0[0] += wh0 * hv.x; ah0[1] += wh0 * hv.y; ah0[2] += wh0 * hv.z; ah0[3] += wh0 * hv.w;
        ah1[0] += wh1 * hv.x; ah1[1] += wh1 * hv.y; ah1[2] += wh1 * hv.z; ah1[3] += wh1 * hv.w;
        ah2[0] += wh2 * hv.x; ah2[1] += wh2 * hv.y; ah2[2] += wh2 * hv.z; ah2[3] += wh2 * hv.w;
    }
    float bi0 = bi[j], bi1 = bi[CDIM + j], bi2 = bi[2 * CDIM + j];
    float bh0 = bh[j], bh1 = bh[CDIM + j], bh2 = bh[2 * CDIM + j];
    float4 hold = *reinterpret_cast<const float4*>(&hs[j * 4]);
    float ho[4] = {hold.x, hold.y, hold.z, hold.w};
    float hn[4];
#pragma unroll
    for (int b = 0; b < 4; b++) {
        float r = 1.f / (1.f + expf(-(ai0[b] + bi0 + ah0[b] + bh0)));
        float z = 1.f / (1.f + expf(-(ai1[b] + bi1 + ah1[b] + bh1)));
        float n = tanhf(ai2[b] + bi2 + r * (ah2[b] + bh2));
        hn[b] = (1.f - z) * n + z * ho[b];
    }
    __syncthreads();   // all reads of hs done before overwrite
    *reinterpret_cast<float4*>(&hs[j * 4]) = make_float4(hn[0], hn[1], hn[2], hn[3]);
    __syncthreads();
}

// ---------------- autoregressive decoder: 128 CTAs x 4 batch rows, 800 internal steps ----
__global__ __launch_bounds__(256, 1) void ar_kernel(
    const float* __restrict__ d1b, const float* __restrict__ d2b,
    const float* __restrict__ b1i, const float* __restrict__ b1h,
    const float* __restrict__ b2i, const float* __restrict__ b2h,
    const float* __restrict__ b3i, const float* __restrict__ b3h,
    const float* __restrict__ ob,
    const int* __restrict__ nbf,
    float* __restrict__ out) {
    __shared__ __align__(16) float x_s[D1K * 4];   // input to d1: cond(256) + prev(40), [k][4]
    __shared__ __align__(16) float t_s[CDIM * 4];  // t1
    __shared__ __align__(16) float h1_s[CDIM * 4];
    __shared__ __align__(16) float h2_s[CDIM * 4];
    __shared__ __align__(16) float h3_s[CDIM * 4];

    int tid = threadIdx.x;
    int bg = blockIdx.x * 4;

    for (int i = tid; i < D1K * 4; i += 256) x_s[i] = 0.f;
    for (int i = tid; i < CDIM * 4; i += 256) {
        h1_s[i] = 0.f; h2_s[i] = 0.f; h3_s[i] = 0.f;
    }
    __syncthreads();

    int steps = nbf[0] * 4;
    int ostride = steps * SUBD;
    const float* cond = g_bufB;   // [b, frame(200), c]

    for (int s = 0; s < steps; s++) {
        int f = s >> 2;
        // load cond rows into x_s[c][b]
#pragma unroll
        for (int q = 0; q < 4; q++)
            x_s[tid * 4 + q] = cond[((bg + q) * 200 + f) * CDIM + tid];
        __syncthreads();

        // d1: tanh([cond;prev] @ d1_w^T + b), K=296
        {
            float bb = d1b[tid];
            float a0 = bb, a1 = bb, a2 = bb, a3 = bb;
#pragma unroll 4
            for (int k = 0; k < D1K; k++) {
                float w = g_d1t[k * CDIM + tid];
                float4 xv = *reinterpret_cast<const float4*>(&x_s[k * 4]);
                a0 += w * xv.x; a1 += w * xv.y; a2 += w * xv.z; a3 += w * xv.w;
            }
            *reinterpret_cast<float4*>(&t_s[tid * 4]) =
                make_float4(tanhf(a0), tanhf(a1), tanhf(a2), tanhf(a3));
        }
        __syncthreads();

        // d2: tanh(t1 @ d2_w^T + b) -> x_s[0..255]
        {
            float bb = d2b[tid];
            float a0 = bb, a1 = bb, a2 = bb, a3 = bb;
#pragma unroll 4
            for (int k = 0; k < CDIM; k++) {
                float w = g_d2t[k * CDIM + tid];
                float4 xv = *reinterpret_cast<const float4*>(&t_s[k * 4]);
                a0 += w * xv.x; a1 += w * xv.y; a2 += w * xv.z; a3 += w * xv.w;
            }
            *reinterpret_cast<float4*>(&x_s[tid * 4]) =
                make_float4(tanhf(a0), tanhf(a1), tanhf(a2), tanhf(a3));
        }
        __syncthreads();

        gru_stage(x_s,  h1_s, g_w1i, g_w1h, b1i, b1h, tid);
        gru_stage(h1_s, h2_s, g_w2i, g_w2h, b2i, b2h, tid);
        gru_stage(h2_s, h3_s, g_w3i, g_w3h, b3i, b3h, tid);

        // output layer: tanh(h3 @ ow^T + ob), 40 cols
        if (tid < SUBD) {
            float bb = ob[tid];
            float a0 = bb, a1 = bb, a2 = bb, a3 = bb;
#pragma unroll 4
            for (int k = 0; k < CDIM; k++) {
                float w = g_owt[k * SUBD + tid];
                float4 hv = *reinterpret_cast<const float4*>(&h3_s[k * 4]);
                a0 += w * hv.x; a1 += w * hv.y; a2 += w * hv.z; a3 += w * hv.w;
            }
            float v[4] = {tanhf(a0), tanhf(a1), tanhf(a2), tanhf(a3)};
#pragma unroll
            for (int b = 0; b < 4; b++) {
                out[(bg + b) * ostride + s * SUBD + tid] = v[b];
                x_s[(CDIM + tid) * 4 + b] = v[b];   // prev for next step
            }
        }
        __syncthreads();
    }
}

// ---------------- launcher ----------------
extern "C" void kernel_launch(void* const* d_in, const int* in_sizes, int n_in,
                              void* d_out, int out_size) {
    const float* feat   = (const float*)d_in[0];
    const float* fd1_w  = (const float*)d_in[1];
    const float* fd1_b  = (const float*)d_in[2];
    const float* c1_w   = (const float*)d_in[3];
    const float* c1_b   = (const float*)d_in[4];
    const float* c2_w   = (const float*)d_in[5];
    const float* c2_b   = (const float*)d_in[6];
    const float* fd2_w  = (const float*)d_in[7];
    const float* fd2_b  = (const float*)d_in[8];
    const float* d1_w   = (const float*)d_in[9];
    const float* d1_b   = (const float*)d_in[10];
    const float* d2_w   = (const float*)d_in[11];
    const float* d2_b   = (const float*)d_in[12];
    const float* g1_wih = (const float*)d_in[13];
    const float* g1_whh = (const float*)d_in[14];
    const float* g1_bih = (const float*)d_in[15];
    const float* g1_bhh = (const float*)d_in[16];
    const float* g2_wih = (const float*)d_in[17];
    const float* g2_whh = (const float*)d_in[18];
    const float* g2_bih = (const float*)d_in[19];
    const float* g2_bhh = (const float*)d_in[20];
    const float* g3_wih = (const float*)d_in[21];
    const float* g3_whh = (const float*)d_in[22];
    const float* g3_bih = (const float*)d_in[23];
    const float* g3_bhh = (const float*)d_in[24];
    const float* ow     = (const float*)d_in[25];
    const float* ob     = (const float*)d_in[26];
    const int*   nbf    = (const int*)d_in[27];
    float* out = (float*)d_out;

    float *pA, *pB, *pfd1t, *pc1t, *pc2t, *pfd2t, *pd1t, *pd2t;
    float *pw1i, *pw1h, *pw2i, *pw2h, *pw3i, *pw3h, *powt;
    cudaGetSymbolAddress((void**)&pA, g_bufA);
    cudaGetSymbolAddress((void**)&pB, g_bufB);
    cudaGetSymbolAddress((void**)&pfd1t, g_fd1t);
    cudaGetSymbolAddress((void**)&pc1t, g_c1t);
    cudaGetSymbolAddress((void**)&pc2t, g_c2t);
    cudaGetSymbolAddress((void**)&pfd2t, g_fd2t);
    cudaGetSymbolAddress((void**)&pd1t, g_d1t);
    cudaGetSymbolAddress((void**)&pd2t, g_d2t);
    cudaGetSymbolAddress((void**)&pw1i, g_w1i);
    cudaGetSymbolAddress((void**)&pw1h, g_w1h);
    cudaGetSymbolAddress((void**)&pw2i, g_w2i);
    cudaGetSymbolAddress((void**)&pw2h, g_w2h);
    cudaGetSymbolAddress((void**)&pw3i, g_w3i);
    cudaGetSymbolAddress((void**)&pw3h, g_w3h);
    cudaGetSymbolAddress((void**)&powt, g_owt);

    auto T = [](const float* src, float* dst, int N, int K) {
        int n = N * K;
        transpose_k<<<(n + 255) / 256, 256>>>(src, dst, N, K);
    };
    T(fd1_w, pfd1t, CDIM, NFEAT);
    T(c1_w,  pc1t,  CDIM, 768);
    T(c2_w,  pc2t,  CDIM, 768);
    T(fd2_w, pfd2t, CDIM, CDIM);
    T(d1_w,  pd1t,  CDIM, D1K);
    T(d2_w,  pd2t,  CDIM, CDIM);
    T(g1_wih, pw1i, 768, CDIM);
    T(g1_whh, pw1h, 768, CDIM);
    T(g2_wih, pw2i, 768, CDIM);
    T(g2_whh, pw2h, 768, CDIM);
    T(g3_wih, pw3i, 768, CDIM);
    T(g3_whh, pw3h, 768, CDIM);
    T(ow,     powt, SUBD, CDIM);

    // cond net
    fd1_kernel<<<BATCH * TFEAT, 256>>>(feat, fd1_b);
    conv_kernel<3><<<dim3(13, BATCH), 256>>>(pA, pc1t, c1_b, pB, 204, 202);
    conv_kernel<3><<<dim3(13, BATCH), 256>>>(pB, pc2t, c2_b, pA, 202, 200);
    conv_kernel<1><<<dim3(13, BATCH), 256>>>(pA, pfd2t, fd2_b, pB, 200, 200);

    // autoregressive decoder
    ar_kernel<<<128, 256>>>(d1_b, d2_b,
                            g1_bih, g1_bhh, g2_bih, g2_bhh, g3_bih, g3_bhh,
                            ob, nbf, out);
}

// round 3
// speedup vs baseline: 1.5766x; 1.5766x over previous
#include <cuda_runtime.h>
#include <math.h>

#define BATCH 512
#define TFEAT 204
#define NFEAT 20
#define CDIM  256
#define SUBD  40
#define D1K   296   // CDIM + SUBD
#define NSLICE 32
#define NGRP   4
#define GROWS  128  // batch rows per group
#define NCTA   128

// ---------------- scratch (device globals; no runtime allocation) ----------------
__device__ float g_bufA[BATCH * TFEAT * CDIM];
__device__ float g_bufB[BATCH * TFEAT * CDIM];

__device__ float g_fd1t[NFEAT * CDIM];
__device__ float g_c1t[768 * CDIM];
__device__ float g_c2t[768 * CDIM];
__device__ float g_fd2t[CDIM * CDIM];

// AR activation state (exchanged through L2)
__device__ float g_t1[BATCH * CDIM];
__device__ float g_t2[BATCH * CDIM];
__device__ float g_h[2][3][BATCH * CDIM];   // ping-pong x 3 GRU layers
__device__ float g_prev[BATCH * SUBD];
__device__ int   g_bar[NGRP];

// ---------------- smem layout for AR kernel (floats) ----------------
// pads chosen for conflict-free 8-way LDS.128: 300 mod 32 = 12, 260 mod 32 = 4
#define PD1 300
#define PDK 260
#define O_WD1  0                       // [8][300]
#define O_WD2  2400                    // [8][260]
#define O_GRU0 4480                    // per gru: wih [3][8][260]=6240, whh 6240
#define GRU_STRIDE 12480
#define O_WOW  (O_GRU0 + 3*GRU_STRIDE) // 41920, [2][260]
#define O_BD1  (O_WOW + 520)           // 42440 [8]
#define O_BD2  (O_BD1 + 8)             // [8]
#define O_BI0  (O_BD2 + 8)             // per gru: bi[24], bh[24]
#define O_OB   (O_BI0 + 3*48)          // [2]
#define SM_FLOATS (O_OB + 2)           // 42602
#define SM_BYTES  (SM_FLOATS * 4)

// ---------------- transpose: dst[k*N + n] = src[n*K + k] ----------------
__global__ void transpose_k(const float* __restrict__ src, float* __restrict__ dst,
                            int N, int K) {
    int idx = blockIdx.x * 256 + threadIdx.x;
    if (idx < N * K) {
        int n = idx / K;
        int k = idx - n * K;
        dst[k * N + n] = src[idx];
    }
}

// ---------------- fd1 ----------------
__global__ void fd1_kernel(const float* __restrict__ feat, const float* __restrict__ bias) {
    __shared__ float fs[NFEAT];
    int row = blockIdx.x;
    int tid = threadIdx.x;
    if (tid < NFEAT) fs[tid] = feat[row * NFEAT + tid];
    __syncthreads();
    float acc = bias[tid];
#pragma unroll
    for (int k = 0; k < NFEAT; k++)
        acc += g_fd1t[k * CDIM + tid] * fs[k];
    g_bufA[row * CDIM + tid] = tanhf(acc);
}

// ---------------- conv/fc ----------------
template <int KW>
__global__ void conv_kernel(const float* __restrict__ in, const float* __restrict__ wt,
                            const float* __restrict__ bias, float* __restrict__ out,
                            int T_in, int T_out) {
    const int TT = 16;
    const int ROWS = TT + KW - 1;
    const int PAD = 258;
    __shared__ float in_s[ROWS * PAD];

    int b = blockIdx.y;
    int t0 = blockIdx.x * TT;
    int tid = threadIdx.x;

#pragma unroll
    for (int r = 0; r < ROWS; r++) {
        int t = t0 + r;
        in_s[r * PAD + tid] = (t < T_in) ? in[(b * T_in + t) * CDIM + tid] : 0.f;
    }
    __syncthreads();

    int tg = tid & 3;
    int c0 = (tid >> 2) * 4;

    float acc[4][4];
#pragma unroll
    for (int a = 0; a < 4; a++)
#pragma unroll
        for (int c = 0; c < 4; c++) acc[a][c] = 0.f;

#pragma unroll 2
    for (int i = 0; i < CDIM; i++) {
#pragma unroll
        for (int j = 0; j < KW; j++) {
            float4 w = *reinterpret_cast<const float4*>(&wt[(i * KW + j) * CDIM + c0]);
#pragma unroll
            for (int tt = 0; tt < 4; tt++) {
                float xv = in_s[(tg * 4 + tt + j) * PAD + i];
                acc[tt][0] += xv * w.x;
                acc[tt][1] += xv * w.y;
                acc[tt][2] += xv * w.z;
                acc[tt][3] += xv * w.w;
            }
        }
    }

    float4 bv = *reinterpret_cast<const float4*>(&bias[c0]);
#pragma unroll
    for (int tt = 0; tt < 4; tt++) {
        int t = t0 + tg * 4 + tt;
        if (t < T_out) {
            float4 o;
            o.x = tanhf(acc[tt][0] + bv.x);
            o.y = tanhf(acc[tt][1] + bv.y);
            o.z = tanhf(acc[tt][2] + bv.z);
            o.w = tanhf(acc[tt][3] + bv.w);
            *reinterpret_cast<float4*>(&out[(b * T_out + t) * CDIM + c0]) = o;
        }
    }
}

// ---------------- group barrier (monotonic counter, 32 CTAs/group) ----------------
__device__ __forceinline__ void group_barrier(int grp, int target) {
    __threadfence();             // every thread fences its own global stores
    __syncthreads();
    if (threadIdx.x == 0) {
        atomicAdd(&g_bar[grp], 1);
        volatile int* vb = (volatile int*)&g_bar[grp];
        while (*vb < target) { }
    }
    __syncthreads();
}

__device__ __forceinline__ float sigf(float v) {
    return 1.f / (1.f + expf(-v));
}

// ---------------- dense slice: y[:, scol] = tanh(x @ w_slice + b), K=256 ----------------
__device__ __forceinline__ void dense256(const float* __restrict__ sw,   // smem [8][PDK]
                                         const float* __restrict__ sb,   // smem [8]
                                         const float* __restrict__ x,    // gmem [row][256]
                                         float* __restrict__ y,          // gmem [row][256]
                                         int c, int gr0, int scol) {
    float bb = sb[c];
    float a0 = bb, a1 = bb, a2 = bb, a3 = bb;
    const float* wp = sw + c * PDK;
    const float* x0 = x + (size_t)gr0 * CDIM;
#pragma unroll 4
    for (int k4 = 0; k4 < 64; k4++) {
        float4 w = *reinterpret_cast<const float4*>(wp + k4 * 4);
        float4 v0 = __ldcg(reinterpret_cast<const float4*>(x0 + k4 * 4));
        float4 v1 = __ldcg(reinterpret_cast<const float4*>(x0 + CDIM + k4 * 4));
        float4 v2 = __ldcg(reinterpret_cast<const float4*>(x0 + 2 * CDIM + k4 * 4));
        float4 v3 = __ldcg(reinterpret_cast<const float4*>(x0 + 3 * CDIM + k4 * 4));
        a0 += v0.x * w.x + v0.y * w.y + v0.z * w.z + v0.w * w.w;
        a1 += v1.x * w.x + v1.y * w.y + v1.z * w.z + v1.w * w.w;
        a2 += v2.x * w.x + v2.y * w.y + v2.z * w.z + v2.w * w.w;
        a3 += v3.x * w.x + v3.y * w.y + v3.z * w.z + v3.w * w.w;
    }
    float* y0 = y + (size_t)gr0 * CDIM + scol;
    __stcg(y0,            tanhf(a0));
    __stcg(y0 + CDIM,     tanhf(a1));
    __stcg(y0 + 2 * CDIM, tanhf(a2));
    __stcg(y0 + 3 * CDIM, tanhf(a3));
}

// ---------------- GRU slice: 8 h-columns, 4 rows per thread ----------------
__device__ __forceinline__ void gru_slice(const float* __restrict__ sm,
                                          int gl,                           // gru index 0..2
                                          const float* __restrict__ x,     // gmem [row][256]
                                          const float* __restrict__ ho,    // old h
                                          float* __restrict__ hn,          // new h
                                          int c, int gr0, int scol) {
    const float* wih = sm + O_GRU0 + gl * GRU_STRIDE;
    const float* whh = wih + 3 * 8 * PDK;
    const float* wr = wih + (0 * 8 + c) * PDK;
    const float* wz = wih + (1 * 8 + c) * PDK;
    const float* wn = wih + (2 * 8 + c) * PDK;
    const float* vr = whh + (0 * 8 + c) * PDK;
    const float* vz = whh + (1 * 8 + c) * PDK;
    const float* vn = whh + (2 * 8 + c) * PDK;

    float air[4], aiz[4], ain[4], ahr[4], ahz[4], ahn[4];
#pragma unroll
    for (int rr = 0; rr < 4; rr++) {
        air[rr] = 0.f; aiz[rr] = 0.f; ain[rr] = 0.f;
        ahr[rr] = 0.f; ahz[rr] = 0.f; ahn[rr] = 0.f;
    }
    const float* x0 = x + (size_t)gr0 * CDIM;
    const float* h0 = ho + (size_t)gr0 * CDIM;

#pragma unroll 2
    for (int k4 = 0; k4 < 64; k4++) {
        float4 Wr = *reinterpret_cast<const float4*>(wr + k4 * 4);
        float4 Wz = *reinterpret_cast<const float4*>(wz + k4 * 4);
        float4 Wn = *reinterpret_cast<const float4*>(wn + k4 * 4);
        float4 Vr = *reinterpret_cast<const float4*>(vr + k4 * 4);
        float4 Vz = *reinterpret_cast<const float4*>(vz + k4 * 4);
        float4 Vn = *reinterpret_cast<const float4*>(vn + k4 * 4);
#pragma unroll
        for (int rr = 0; rr < 4; rr++) {
            float4 xv = __ldcg(reinterpret_cast<const float4*>(x0 + rr * CDIM + k4 * 4));
            float4 hv = __ldcg(reinterpret_cast<const float4*>(h0 + rr * CDIM + k4 * 4));
            air[rr] += xv.x * Wr.x + xv.y * Wr.y + xv.z * Wr.z + xv.w * Wr.w;
            aiz[rr] += xv.x * Wz.x + xv.y * Wz.y + xv.z * Wz.z + xv.w * Wz.w;
            ain[rr] += xv.x * Wn.x + xv.y * Wn.y + xv.z * Wn.z + xv.w * Wn.w;
            ahr[rr] += hv.x * Vr.x + hv.y * Vr.y + hv.z * Vr.z + hv.w * Vr.w;
            ahz[rr] += hv.x * Vz.x + hv.y * Vz.y + hv.z * Vz.z + hv.w * Vz.w;
            ahn[rr] += hv.x * Vn.x + hv.y * Vn.y + hv.z * Vn.z + hv.w * Vn.w;
        }
    }
    const float* bi = sm + O_BI0 + gl * 48;
    const float* bh = bi + 24;
    float bir = bi[c], biz = bi[8 + c], bin = bi[16 + c];
    float bhr = bh[c], bhz = bh[8 + c], bhn = bh[16 + c];
#pragma unroll
    for (int rr = 0; rr < 4; rr++) {
        float r = sigf(air[rr] + bir + ahr[rr] + bhr);
        float z = sigf(aiz[rr] + biz + ahz[rr] + bhz);
        float n = tanhf(ain[rr] + bin + r * (ahn[rr] + bhn));
        float hold = __ldcg(h0 + rr * CDIM + scol);
        __stcg(hn + (size_t)(gr0 + rr) * CDIM + scol, (1.f - z) * n + z * hold);
    }
}

// ---------------- persistent AR kernel: 4 groups x 32 model slices ----------------
__global__ void __launch_bounds__(256, 1) ar_kernel(
    const float* __restrict__ d1_w, const float* __restrict__ d1_b,
    const float* __restrict__ d2_w, const float* __restrict__ d2_b,
    const float* __restrict__ w1i, const float* __restrict__ w1h,
    const float* __restrict__ b1i, const float* __restrict__ b1h,
    const float* __restrict__ w2i, const float* __restrict__ w2h,
    const float* __restrict__ b2i, const float* __restrict__ b2h,
    const float* __restrict__ w3i, const float* __restrict__ w3h,
    const float* __restrict__ b3i, const float* __restrict__ b3h,
    const float* __restrict__ ow,  const float* __restrict__ ob,
    const int* __restrict__ nbf,   float* __restrict__ out) {
    extern __shared__ float sm[];

    int tid = threadIdx.x;
    int s = blockIdx.x & (NSLICE - 1);   // model slice 0..31
    int grp = blockIdx.x >> 5;           // batch group 0..3
    int grow0 = grp * GROWS;

    // ---- load resident weight slice into smem ----
    for (int e = tid; e < 8 * D1K; e += 256) {
        int r = e / D1K, k = e - r * D1K;
        sm[O_WD1 + r * PD1 + k] = d1_w[(s * 8 + r) * D1K + k];
    }
    for (int e = tid; e < 8 * CDIM; e += 256) {
        int r = e >> 8, k = e & 255;
        sm[O_WD2 + r * PDK + k] = d2_w[(s * 8 + r) * CDIM + k];
    }
    const float* wis[3] = {w1i, w2i, w3i};
    const float* whs[3] = {w1h, w2h, w3h};
    const float* bis[3] = {b1i, b2i, b3i};
    const float* bhs[3] = {b1h, b2h, b3h};
    for (int l = 0; l < 3; l++) {
        for (int e = tid; e < 24 * CDIM; e += 256) {
            int gr = e >> 8, k = e & 255;   // gr = g*8 + r
            int g = gr >> 3, r = gr & 7;
            sm[O_GRU0 + l * GRU_STRIDE + gr * PDK + k] = wis[l][(g * CDIM + s * 8 + r) * CDIM + k];
            sm[O_GRU0 + l * GRU_STRIDE + 3 * 8 * PDK + gr * PDK + k] =
                whs[l][(g * CDIM + s * 8 + r) * CDIM + k];
        }
        if (tid < 24) {
            int g = tid >> 3, r = tid & 7;
            sm[O_BI0 + l * 48 + tid] = bis[l][g * CDIM + s * 8 + r];
            sm[O_BI0 + l * 48 + 24 + tid] = bhs[l][g * CDIM + s * 8 + r];
        }
    }
    if (s < 20) {
        for (int e = tid; e < 2 * CDIM; e += 256) {
            int r = e >> 8, k = e & 255;
            sm[O_WOW + r * PDK + k] = ow[(s * 2 + r) * CDIM + k];
        }
        if (tid < 2) sm[O_OB + tid] = ob[s * 2 + tid];
    }
    if (tid < 8) {
        sm[O_BD1 + tid] = d1_b[s * 8 + tid];
        sm[O_BD2 + tid] = d2_b[s * 8 + tid];
    }
    __syncthreads();

    int c = tid & 7;
    int rg = tid >> 3;
    int gr0 = grow0 + rg * 4;        // this thread's first global row
    int scol = s * 8 + c;

    int steps = nbf[0] * 4;
    int ostride = steps * SUBD;
    int bar_ep = 0;

    for (int st = 0; st < steps; st++) {
        int f = st >> 2;
        int p = st & 1;
        const float* h1o = g_h[p][0];     float* h1n = g_h[p ^ 1][0];
        const float* h2o = g_h[p][1];     float* h2n = g_h[p ^ 1][1];
        const float* h3o = g_h[p][2];     float* h3n = g_h[p ^ 1][2];

        // ---- d1: tanh([cond, prev] @ w + b) -> t1 ----
        {
            float bb = sm[O_BD1 + c];
            float a0 = bb, a1 = bb, a2 = bb, a3 = bb;
            const float* wp = sm + O_WD1 + c * PD1;
            const float* cb = g_bufB + ((size_t)gr0 * 200 + f) * CDIM;
#pragma unroll 4
            for (int k4 = 0; k4 < 64; k4++) {
                float4 w = *reinterpret_cast<const float4*>(wp + k4 * 4);
                float4 v0 = __ldcg(reinterpret_cast<const float4*>(cb + k4 * 4));
                float4 v1 = __ldcg(reinterpret_cast<const float4*>(cb + 200 * CDIM + k4 * 4));
                float4 v2 = __ldcg(reinterpret_cast<const float4*>(cb + 400 * CDIM + k4 * 4));
                float4 v3 = __ldcg(reinterpret_cast<const float4*>(cb + 600 * CDIM + k4 * 4));
                a0 += v0.x * w.x + v0.y * w.y + v0.z * w.z + v0.w * w.w;
                a1 += v1.x * w.x + v1.y * w.y + v1.z * w.z + v1.w * w.w;
                a2 += v2.x * w.x + v2.y * w.y + v2.z * w.z + v2.w * w.w;
                a3 += v3.x * w.x + v3.y * w.y + v3.z * w.z + v3.w * w.w;
            }
            const float* pb = g_prev + (size_t)gr0 * SUBD;
#pragma unroll
            for (int k4 = 64; k4 < 74; k4++) {
                float4 w = *reinterpret_cast<const float4*>(wp + k4 * 4);
                int ko = (k4 - 64) * 4;
                float4 v0 = __ldcg(reinterpret_cast<const float4*>(pb + ko));
                float4 v1 = __ldcg(reinterpret_cast<const float4*>(pb + SUBD + ko));
                float4 v2 = __ldcg(reinterpret_cast<const float4*>(pb + 2 * SUBD + ko));
                float4 v3 = __ldcg(reinterpret_cast<const float4*>(pb + 3 * SUBD + ko));
                a0 += v0.x * w.x + v0.y * w.y + v0.z * w.z + v0.w * w.w;
                a1 += v1.x * w.x + v1.y * w.y + v1.z * w.z + v1.w * w.w;
                a2 += v2.x * w.x + v2.y * w.y + v2.z * w.z + v2.w * w.w;
                a3 += v3.x * w.x + v3.y * w.y + v3.z * w.z + v3.w * w.w;
            }
            float* y0 = g_t1 + (size_t)gr0 * CDIM + scol;
            __stcg(y0,            tanhf(a0));
            __stcg(y0 + CDIM,     tanhf(a1));
            __stcg(y0 + 2 * CDIM, tanhf(a2));
            __stcg(y0 + 3 * CDIM, tanhf(a3));
        }
        group_barrier(grp, (++bar_ep) * NSLICE);

        // ---- d2 ----
        dense256(sm + O_WD2, sm + O_BD2, g_t1, g_t2, c, gr0, scol);
        group_barrier(grp, (++bar_ep) * NSLICE);

        // ---- GRUs ----
        gru_slice(sm, 0, g_t2, h1o, h1n, c, gr0, scol);
        group_barrier(grp, (++bar_ep) * NSLICE);
        gru_slice(sm, 1, h1n, h2o, h2n, c, gr0, scol);
        group_barrier(grp, (++bar_ep) * NSLICE);
        gru_slice(sm, 2, h2n, h3o, h3n, c, gr0, scol);
        group_barrier(grp, (++bar_ep) * NSLICE);

        // ---- output layer: slices 0..19, 2 cols each ----
        if (s < 20) {
            int c2 = tid & 1;
            int row = grow0 + (tid >> 1);
            int col = s * 2 + c2;
            float acc = sm[O_OB + c2];
            const float* wp = sm + O_WOW + c2 * PDK;
            const float* hb = h3n + (size_t)row * CDIM;
#pragma unroll 4
            for (int k4 = 0; k4 < 64; k4++) {
                float4 w = *reinterpret_cast<const float4*>(wp + k4 * 4);
                float4 hv = __ldcg(reinterpret_cast<const float4*>(hb + k4 * 4));
                acc += hv.x * w.x + hv.y * w.y + hv.z * w.z + hv.w * w.w;
            }
            float v = tanhf(acc);
            out[(size_t)row * ostride + st * SUBD + col] = v;
            __stcg(&g_prev[row * SUBD + col], v);
        }
        group_barrier(grp, (++bar_ep) * NSLICE);
    }
}

// ---------------- launcher ----------------
extern "C" void kernel_launch(void* const* d_in, const int* in_sizes, int n_in,
                              void* d_out, int out_size) {
    const float* feat   = (const float*)d_in[0];
    const float* fd1_w  = (const float*)d_in[1];
    const float* fd1_b  = (const float*)d_in[2];
    const float* c1_w   = (const float*)d_in[3];
    const float* c1_b   = (const float*)d_in[4];
    const float* c2_w   = (const float*)d_in[5];
    const float* c2_b   = (const float*)d_in[6];
    const float* fd2_w  = (const float*)d_in[7];
    const float* fd2_b  = (const float*)d_in[8];
    const float* d1_w   = (const float*)d_in[9];
    const float* d1_b   = (const float*)d_in[10];
    const float* d2_w   = (const float*)d_in[11];
    const float* d2_b   = (const float*)d_in[12];
    const float* g1_wih = (const float*)d_in[13];
    const float* g1_whh = (const float*)d_in[14];
    const float* g1_bih = (const float*)d_in[15];
    const float* g1_bhh = (const float*)d_in[16];
    const float* g2_wih = (const float*)d_in[17];
    const float* g2_whh = (const float*)d_in[18];
    const float* g2_bih = (const float*)d_in[19];
    const float* g2_bhh = (const float*)d_in[20];
    const float* g3_wih = (const float*)d_in[21];
    const float* g3_whh = (const float*)d_in[22];
    const float* g3_bih = (const float*)d_in[23];
    const float* g3_bhh = (const float*)d_in[24];
    const float* ow     = (const float*)d_in[25];
    const float* ob     = (const float*)d_in[26];
    const int*   nbf    = (const int*)d_in[27];
    float* out = (float*)d_out;

    float *pA, *pB, *pfd1t, *pc1t, *pc2t, *pfd2t, *pH, *pPrev;
    int* pBar;
    cudaGetSymbolAddress((void**)&pA, g_bufA);
    cudaGetSymbolAddress((void**)&pB, g_bufB);
    cudaGetSymbolAddress((void**)&pfd1t, g_fd1t);
    cudaGetSymbolAddress((void**)&pc1t, g_c1t);
    cudaGetSymbolAddress((void**)&pc2t, g_c2t);
    cudaGetSymbolAddress((void**)&pfd2t, g_fd2t);
    cudaGetSymbolAddress((void**)&pH, g_h);
    cudaGetSymbolAddress((void**)&pPrev, g_prev);
    cudaGetSymbolAddress((void**)&pBar, g_bar);

    // zero AR state + barrier counters (graph-capturable)
    cudaMemsetAsync(pH, 0, 2 * 3 * BATCH * CDIM * sizeof(float));
    cudaMemsetAsync(pPrev, 0, BATCH * SUBD * sizeof(float));
    cudaMemsetAsync(pBar, 0, NGRP * sizeof(int));

    auto T = [](const float* src, float* dst, int N, int K) {
        int n = N * K;
        transpose_k<<<(n + 255) / 256, 256>>>(src, dst, N, K);
    };
    T(fd1_w, pfd1t, CDIM, NFEAT);
    T(c1_w,  pc1t,  CDIM, 768);
    T(c2_w,  pc2t,  CDIM, 768);
    T(fd2_w, pfd2t, CDIM, CDIM);

    // cond net
    fd1_kernel<<<BATCH * TFEAT, 256>>>(feat, fd1_b);
    conv_kernel<3><<<dim3(13, BATCH), 256>>>(pA, pc1t, c1_b, pB, 204, 202);
    conv_kernel<3><<<dim3(13, BATCH), 256>>>(pB, pc2t, c2_b, pA, 202, 200);
    conv_kernel<1><<<dim3(13, BATCH), 256>>>(pA, pfd2t, fd2_b, pB, 200, 200);

    // persistent autoregressive decoder (weights resident in smem)
    cudaFuncSetAttribute(ar_kernel, cudaFuncAttributeMaxDynamicSharedMemorySize, SM_BYTES);
    ar_kernel<<<NCTA, 256, SM_BYTES>>>(
        d1_w, d1_b, d2_w, d2_b,
        g1_wih, g1_whh, g1_bih, g1_bhh,
        g2_wih, g2_whh, g2_bih, g2_bhh,
        g3_wih, g3_whh, g3_bih, g3_bhh,
        ow, ob, nbf, out);
}

// round 4
// speedup vs baseline: 1.6428x; 1.0420x over previous
#include <cuda_runtime.h>
#include <math.h>

typedef unsigned long long ull;

#define BATCH 512
#define TFEAT 204
#define NFEAT 20
#define CDIM  256
#define SUBD  40
#define D1K   296   // CDIM + SUBD
#define NSLICE 32
#define NGRP   4
#define GROWS  128  // batch rows per group
#define NCTA   128
#define NTHR   512

// ---------------- scratch (device globals) ----------------
__device__ float g_bufA[BATCH * TFEAT * CDIM];
__device__ float g_bufB[BATCH * TFEAT * CDIM];

__device__ float g_fd1t[NFEAT * CDIM];
__device__ float g_c1t[768 * CDIM];
__device__ float g_c2t[768 * CDIM];
__device__ float g_fd2t[CDIM * CDIM];

// AR activation state (exchanged through L2)
__device__ float g_t1[BATCH * CDIM];
__device__ float g_t2[BATCH * CDIM];
__device__ float g_h[2][3][BATCH * CDIM];
__device__ float g_prev[BATCH * SUBD];
__device__ int   g_bar[NGRP];

// ---------------- smem layout (floats) ----------------
#define PD1 300
#define PDK 260
#define O_WD1  0                       // [8][300]
#define O_WD2  2400                    // [8][260]
#define O_GRU0 4480                    // per gru: wih [3][8][260], whh same
#define GRU_STRIDE 12480
#define O_WOW  (O_GRU0 + 3*GRU_STRIDE) // [2][260]
#define O_BD1  (O_WOW + 520)
#define O_BD2  (O_BD1 + 8)
#define O_BI0  (O_BD2 + 8)             // per gru: bi[24], bh[24]
#define O_OB   (O_BI0 + 3*48)
#define O_XS   42604                   // staging buf X: [128][44]
#define O_HS   (O_XS + 128*44)         // staging buf H: [128][44]
#define SM_FLOATS (O_HS + 128*44)
#define SM_BYTES  (SM_FLOATS * 4)      // 215472 B

// ---------------- f32x2 helpers ----------------
__device__ __forceinline__ void fma2(ull& d, ull a, ull b) {
    asm("fma.rn.f32x2 %0, %1, %2, %0;" : "+l"(d) : "l"(a), "l"(b));
}
__device__ __forceinline__ float red2(ull v) {
    union { ull u; float2 f; } t; t.u = v;
    return t.f.x + t.f.y;
}
union F4U { float4 f; ull u[2]; };

__device__ __forceinline__ float sigf(float v) {
    return 1.f / (1.f + expf(-v));
}

// ---------------- transpose ----------------
__global__ void transpose_k(const float* __restrict__ src, float* __restrict__ dst,
                            int N, int K) {
    int idx = blockIdx.x * 256 + threadIdx.x;
    if (idx < N * K) {
        int n = idx / K;
        int k = idx - n * K;
        dst[k * N + n] = src[idx];
    }
}

// ---------------- fd1 ----------------
__global__ void fd1_kernel(const float* __restrict__ feat, const float* __restrict__ bias) {
    __shared__ float fs[NFEAT];
    int row = blockIdx.x;
    int tid = threadIdx.x;
    if (tid < NFEAT) fs[tid] = feat[row * NFEAT + tid];
    __syncthreads();
    float acc = bias[tid];
#pragma unroll
    for (int k = 0; k < NFEAT; k++)
        acc += g_fd1t[k * CDIM + tid] * fs[k];
    g_bufA[row * CDIM + tid] = tanhf(acc);
}

// ---------------- conv/fc with f32x2 ----------------
template <int KW>
__global__ void conv_kernel(const float* __restrict__ in, const float* __restrict__ wt,
                            const float* __restrict__ bias, float* __restrict__ out,
                            int T_in, int T_out) {
    const int TT = 16;
    const int ROWS = TT + KW - 1;
    const int PAD = 258;
    __shared__ float in_s[ROWS * PAD];

    int b = blockIdx.y;
    int t0 = blockIdx.x * TT;
    int tid = threadIdx.x;

#pragma unroll
    for (int r = 0; r < ROWS; r++) {
        int t = t0 + r;
        in_s[r * PAD + tid] = (t < T_in) ? in[(b * T_in + t) * CDIM + tid] : 0.f;
    }
    __syncthreads();

    int tg = tid & 3;
    int c0 = (tid >> 2) * 4;

    ull acc2[4][2];
#pragma unroll
    for (int a = 0; a < 4; a++) { acc2[a][0] = 0ull; acc2[a][1] = 0ull; }

#pragma unroll 2
    for (int i = 0; i < CDIM; i++) {
#pragma unroll
        for (int j = 0; j < KW; j++) {
            F4U w; w.f = *reinterpret_cast<const float4*>(&wt[(i * KW + j) * CDIM + c0]);
#pragma unroll
            for (int tt = 0; tt < 4; tt++) {
                float xv = in_s[(tg * 4 + tt + j) * PAD + i];
                ull x2;
                asm("mov.b64 %0, {%1, %1};" : "=l"(x2) : "f"(xv));
                fma2(acc2[tt][0], w.u[0], x2);
                fma2(acc2[tt][1], w.u[1], x2);
            }
        }
    }

    float4 bv = *reinterpret_cast<const float4*>(&bias[c0]);
#pragma unroll
    for (int tt = 0; tt < 4; tt++) {
        int t = t0 + tg * 4 + tt;
        if (t < T_out) {
            union { ull u; float2 f; } lo, hi;
            lo.u = acc2[tt][0]; hi.u = acc2[tt][1];
            float4 o;
            o.x = tanhf(lo.f.x + bv.x);
            o.y = tanhf(lo.f.y + bv.y);
            o.z = tanhf(hi.f.x + bv.z);
            o.w = tanhf(hi.f.y + bv.w);
            *reinterpret_cast<float4*>(&out[(b * T_out + t) * CDIM + c0]) = o;
        }
    }
}

// ---------------- group barrier ----------------
__device__ __forceinline__ void group_barrier(int grp, int target) {
    __threadfence();
    __syncthreads();
    if (threadIdx.x == 0) {
        atomicAdd(&g_bar[grp], 1);
        volatile int* vb = (volatile int*)&g_bar[grp];
        while (*vb < target) { }
    }
    __syncthreads();
}

// ---------------- cooperative staging (32-k chunk of 128 rows) ----------------
struct Pre { float4 v[2]; };

__device__ __forceinline__ void stage_ldg(Pre& p, const float* base, int rstride, int k0) {
    int wq = threadIdx.x >> 5, lane = threadIdx.x & 31;
    int f4 = (lane & 7) * 4;
#pragma unroll
    for (int i = 0; i < 2; i++) {
        int row = 8 * wq + 4 * i + (lane >> 3);
        p.v[i] = __ldcg(reinterpret_cast<const float4*>(base + (size_t)row * rstride + k0 + f4));
    }
}
__device__ __forceinline__ void stage_sts(const Pre& p, float* buf) {
    int wq = threadIdx.x >> 5, lane = threadIdx.x & 31;
    int f4 = (lane & 7) * 4;
#pragma unroll
    for (int i = 0; i < 2; i++) {
        int row = 8 * wq + 4 * i + (lane >> 3);
        *reinterpret_cast<float4*>(&buf[row * 44 + f4]) = p.v[i];
    }
}

// ---------------- persistent AR kernel ----------------
__global__ void __launch_bounds__(NTHR, 1) ar_kernel(
    const float* __restrict__ d1_w, const float* __restrict__ d1_b,
    const float* __restrict__ d2_w, const float* __restrict__ d2_b,
    const float* __restrict__ w1i, const float* __restrict__ w1h,
    const float* __restrict__ b1i, const float* __restrict__ b1h,
    const float* __restrict__ w2i, const float* __restrict__ w2h,
    const float* __restrict__ b2i, const float* __restrict__ b2h,
    const float* __restrict__ w3i, const float* __restrict__ w3h,
    const float* __restrict__ b3i, const float* __restrict__ b3h,
    const float* __restrict__ ow,  const float* __restrict__ ob,
    const int* __restrict__ nbf,   float* __restrict__ out) {
    extern __shared__ float sm[];

    int tid = threadIdx.x;
    int s = blockIdx.x & (NSLICE - 1);
    int grp = blockIdx.x >> 5;
    int grow0 = grp * GROWS;

    // ---- load resident weight slice ----
    for (int e = tid; e < 8 * D1K; e += NTHR) {
        int r = e / D1K, k = e - r * D1K;
        sm[O_WD1 + r * PD1 + k] = d1_w[(s * 8 + r) * D1K + k];
    }
    for (int e = tid; e < 8 * CDIM; e += NTHR) {
        int r = e >> 8, k = e & 255;
        sm[O_WD2 + r * PDK + k] = d2_w[(s * 8 + r) * CDIM + k];
    }
    const float* wis[3] = {w1i, w2i, w3i};
    const float* whs[3] = {w1h, w2h, w3h};
    const float* bis[3] = {b1i, b2i, b3i};
    const float* bhs[3] = {b1h, b2h, b3h};
    for (int l = 0; l < 3; l++) {
        for (int e = tid; e < 24 * CDIM; e += NTHR) {
            int gr = e >> 8, k = e & 255;
            int g = gr >> 3, r = gr & 7;
            sm[O_GRU0 + l * GRU_STRIDE + gr * PDK + k] = wis[l][(g * CDIM + s * 8 + r) * CDIM + k];
            sm[O_GRU0 + l * GRU_STRIDE + 3 * 8 * PDK + gr * PDK + k] =
                whs[l][(g * CDIM + s * 8 + r) * CDIM + k];
        }
        if (tid < 24) {
            int g = tid >> 3, r = tid & 7;
            sm[O_BI0 + l * 48 + tid] = bis[l][g * CDIM + s * 8 + r];
            sm[O_BI0 + l * 48 + 24 + tid] = bhs[l][g * CDIM + s * 8 + r];
        }
    }
    if (s < 20) {
        for (int e = tid; e < 2 * CDIM; e += NTHR) {
            int r = e >> 8, k = e & 255;
            sm[O_WOW + r * PDK + k] = ow[(s * 2 + r) * CDIM + k];
        }
        if (tid < 2) sm[O_OB + tid] = ob[s * 2 + tid];
    }
    if (tid < 8) {
        sm[O_BD1 + tid] = d1_b[s * 8 + tid];
        sm[O_BD2 + tid] = d2_b[s * 8 + tid];
    }
    __syncthreads();

    int c = tid & 7;
    int rg = tid >> 3;               // 0..63: rows {rg, rg+64}
    int scol = s * 8 + c;
    int ch_hold = s >> 2;            // chunk containing scol
    int kk_hold = ((s & 3) * 8) + c; // offset within chunk

    float* xs = sm + O_XS;
    float* hs = sm + O_HS;

    int steps = nbf[0] * 4;
    int ostride = steps * SUBD;
    int bar_ep = 0;

    for (int st = 0; st < steps; st++) {
        int f = st >> 2;
        int p = st & 1;
        const float* h1o = g_h[p][0] + (size_t)grow0 * CDIM;
        float*       h1n = g_h[p ^ 1][0] + (size_t)grow0 * CDIM;
        const float* h2o = g_h[p][1] + (size_t)grow0 * CDIM;
        float*       h2n = g_h[p ^ 1][1] + (size_t)grow0 * CDIM;
        const float* h3o = g_h[p][2] + (size_t)grow0 * CDIM;
        float*       h3n = g_h[p ^ 1][2] + (size_t)grow0 * CDIM;
        float*       t1g = g_t1 + (size_t)grow0 * CDIM;
        float*       t2g = g_t2 + (size_t)grow0 * CDIM;
        float*       pvg = g_prev + (size_t)grow0 * SUBD;

        // ================= d1 =================
        {
            // stage prev into hs
            for (int idx = tid; idx < 1280; idx += NTHR) {
                int row = idx / 10;
                int ff = idx - row * 10;
                *reinterpret_cast<float4*>(&hs[row * 44 + ff * 4]) =
                    __ldcg(reinterpret_cast<const float4*>(&pvg[row * SUBD + ff * 4]));
            }
            ull A0 = 0ull, A1 = 0ull;
            const float* wp = sm + O_WD1 + c * PD1;
            const float* cbase = g_bufB + ((size_t)grow0 * 200 + f) * CDIM;
            Pre px;
            stage_ldg(px, cbase, 200 * CDIM, 0);
            stage_sts(px, xs);
            __syncthreads();
            for (int ch = 0; ch < 8; ch++) {
                if (ch < 7) stage_ldg(px, cbase, 200 * CDIM, (ch + 1) * 32);
                int k0 = ch * 32;
#pragma unroll
                for (int k4 = 0; k4 < 8; k4++) {
                    int kk = k4 * 4;
                    F4U W;  W.f  = *reinterpret_cast<const float4*>(wp + k0 + kk);
                    F4U X0; X0.f = *reinterpret_cast<const float4*>(&xs[rg * 44 + kk]);
                    F4U X1; X1.f = *reinterpret_cast<const float4*>(&xs[(rg + 64) * 44 + kk]);
                    fma2(A0, W.u[0], X0.u[0]); fma2(A0, W.u[1], X0.u[1]);
                    fma2(A1, W.u[0], X1.u[0]); fma2(A1, W.u[1], X1.u[1]);
                }
                __syncthreads();
                if (ch < 7) { stage_sts(px, xs); __syncthreads(); }
            }
            // prev tail (k = 256..295) from hs
#pragma unroll
            for (int k4 = 0; k4 < 10; k4++) {
                int kk = k4 * 4;
                F4U W;  W.f  = *reinterpret_cast<const float4*>(wp + 256 + kk);
                F4U P0; P0.f = *reinterpret_cast<const float4*>(&hs[rg * 44 + kk]);
                F4U P1; P1.f = *reinterpret_cast<const float4*>(&hs[(rg + 64) * 44 + kk]);
                fma2(A0, W.u[0], P0.u[0]); fma2(A0, W.u[1], P0.u[1]);
                fma2(A1, W.u[0], P1.u[0]); fma2(A1, W.u[1], P1.u[1]);
            }
            float bb = sm[O_BD1 + c];
            __stcg(&t1g[rg * CDIM + scol], tanhf(red2(A0) + bb));
            __stcg(&t1g[(rg + 64) * CDIM + scol], tanhf(red2(A1) + bb));
        }
        group_barrier(grp, (++bar_ep) * NSLICE);

        // ================= d2 =================
        {
            ull A0 = 0ull, A1 = 0ull;
            const float* wp = sm + O_WD2 + c * PDK;
            Pre px;
            stage_ldg(px, t1g, CDIM, 0);
            stage_sts(px, xs);
            __syncthreads();
            for (int ch = 0; ch < 8; ch++) {
                if (ch < 7) stage_ldg(px, t1g, CDIM, (ch + 1) * 32);
                int k0 = ch * 32;
#pragma unroll
                for (int k4 = 0; k4 < 8; k4++) {
                    int kk = k4 * 4;
                    F4U W;  W.f  = *reinterpret_cast<const float4*>(wp + k0 + kk);
                    F4U X0; X0.f = *reinterpret_cast<const float4*>(&xs[rg * 44 + kk]);
                    F4U X1; X1.f = *reinterpret_cast<const float4*>(&xs[(rg + 64) * 44 + kk]);
                    fma2(A0, W.u[0], X0.u[0]); fma2(A0, W.u[1], X0.u[1]);
                    fma2(A1, W.u[0], X1.u[0]); fma2(A1, W.u[1], X1.u[1]);
                }
                __syncthreads();
                if (ch < 7) { stage_sts(px, xs); __syncthreads(); }
            }
            float bb = sm[O_BD2 + c];
            __stcg(&t2g[rg * CDIM + scol], tanhf(red2(A0) + bb));
            __stcg(&t2g[(rg + 64) * CDIM + scol], tanhf(red2(A1) + bb));
        }
        group_barrier(grp, (++bar_ep) * NSLICE);

        // ================= 3 GRU layers =================
        const float* xsrcs[3] = {t2g, h1n, h2n};
        const float* hsrcs[3] = {h1o, h2o, h3o};
        float*       hdsts[3] = {h1n, h2n, h3n};
        for (int gl = 0; gl < 3; gl++) {
            const float* xsrc = xsrcs[gl];
            const float* hsrc = hsrcs[gl];
            float*       hdst = hdsts[gl];

            const float* wb = sm + O_GRU0 + gl * GRU_STRIDE;
            const float* wr = wb + (0 * 8 + c) * PDK;
            const float* wz = wb + (1 * 8 + c) * PDK;
            const float* wn = wb + (2 * 8 + c) * PDK;
            const float* vr = wb + 3 * 8 * PDK + (0 * 8 + c) * PDK;
            const float* vz = wb + 3 * 8 * PDK + (1 * 8 + c) * PDK;
            const float* vn = wb + 3 * 8 * PDK + (2 * 8 + c) * PDK;

            ull Air0 = 0, Aiz0 = 0, Ain0 = 0, Ahr0 = 0, Ahz0 = 0, Ahn0 = 0;
            ull Air1 = 0, Aiz1 = 0, Ain1 = 0, Ahr1 = 0, Ahz1 = 0, Ahn1 = 0;
            float hold0 = 0.f, hold1 = 0.f;

            Pre px, ph;
            stage_ldg(px, xsrc, CDIM, 0);
            stage_ldg(ph, hsrc, CDIM, 0);
            stage_sts(px, xs);
            stage_sts(ph, hs);
            __syncthreads();
            for (int ch = 0; ch < 8; ch++) {
                if (ch < 7) {
                    stage_ldg(px, xsrc, CDIM, (ch + 1) * 32);
                    stage_ldg(ph, hsrc, CDIM, (ch + 1) * 32);
                }
                int k0 = ch * 32;
#pragma unroll
                for (int k4 = 0; k4 < 8; k4++) {
                    int kk = k4 * 4;
                    int gk = k0 + kk;
                    F4U Wr; Wr.f = *reinterpret_cast<const float4*>(wr + gk);
                    F4U Wz; Wz.f = *reinterpret_cast<const float4*>(wz + gk);
                    F4U Wn; Wn.f = *reinterpret_cast<const float4*>(wn + gk);
                    F4U Vr; Vr.f = *reinterpret_cast<const float4*>(vr + gk);
                    F4U Vz; Vz.f = *reinterpret_cast<const float4*>(vz + gk);
                    F4U Vn; Vn.f = *reinterpret_cast<const float4*>(vn + gk);
                    F4U X0; X0.f = *reinterpret_cast<const float4*>(&xs[rg * 44 + kk]);
                    F4U X1; X1.f = *reinterpret_cast<const float4*>(&xs[(rg + 64) * 44 + kk]);
                    F4U H0; H0.f = *reinterpret_cast<const float4*>(&hs[rg * 44 + kk]);
                    F4U H1; H1.f = *reinterpret_cast<const float4*>(&hs[(rg + 64) * 44 + kk]);
                    fma2(Air0, Wr.u[0], X0.u[0]); fma2(Air0, Wr.u[1], X0.u[1]);
                    fma2(Aiz0, Wz.u[0], X0.u[0]); fma2(Aiz0, Wz.u[1], X0.u[1]);
                    fma2(Ain0, Wn.u[0], X0.u[0]); fma2(Ain0, Wn.u[1], X0.u[1]);
                    fma2(Ahr0, Vr.u[0], H0.u[0]); fma2(Ahr0, Vr.u[1], H0.u[1]);
                    fma2(Ahz0, Vz.u[0], H0.u[0]); fma2(Ahz0, Vz.u[1], H0.u[1]);
                    fma2(Ahn0, Vn.u[0], H0.u[0]); fma2(Ahn0, Vn.u[1], H0.u[1]);
                    fma2(Air1, Wr.u[0], X1.u[0]); fma2(Air1, Wr.u[1], X1.u[1]);
                    fma2(Aiz1, Wz.u[0], X1.u[0]); fma2(Aiz1, Wz.u[1], X1.u[1]);
                    fma2(Ain1, Wn.u[0], X1.u[0]); fma2(Ain1, Wn.u[1], X1.u[1]);
                    fma2(Ahr1, Vr.u[0], H1.u[0]); fma2(Ahr1, Vr.u[1], H1.u[1]);
                    fma2(Ahz1, Vz.u[0], H1.u[0]); fma2(Ahz1, Vz.u[1], H1.u[1]);
                    fma2(Ahn1, Vn.u[0], H1.u[0]); fma2(Ahn1, Vn.u[1], H1.u[1]);
                }
                if (ch == ch_hold) {
                    hold0 = hs[rg * 44 + kk_hold];
                    hold1 = hs[(rg + 64) * 44 + kk_hold];
                }
                __syncthreads();
                if (ch < 7) {
                    stage_sts(px, xs);
                    stage_sts(ph, hs);
                    __syncthreads();
                }
            }
            const float* bi = sm + O_BI0 + gl * 48;
            const float* bh = bi + 24;
            float bir = bi[c], biz = bi[8 + c], bin = bi[16 + c];
            float bhr = bh[c], bhz = bh[8 + c], bhn = bh[16 + c];
            {
                float r = sigf(red2(Air0) + bir + red2(Ahr0) + bhr);
                float z = sigf(red2(Aiz0) + biz + red2(Ahz0) + bhz);
                float n = tanhf(red2(Ain0) + bin + r * (red2(Ahn0) + bhn));
                __stcg(&hdst[rg * CDIM + scol], (1.f - z) * n + z * hold0);
            }
            {
                float r = sigf(red2(Air1) + bir + red2(Ahr1) + bhr);
                float z = sigf(red2(Aiz1) + biz + red2(Ahz1) + bhz);
                float n = tanhf(red2(Ain1) + bin + r * (red2(Ahn1) + bhn));
                __stcg(&hdst[(rg + 64) * CDIM + scol], (1.f - z) * n + z * hold1);
            }
            group_barrier(grp, (++bar_ep) * NSLICE);
        }

        // ================= output layer (slices 0..19) =================
        if (s < 20) {
            ull A = 0ull;
            int lr = tid >> 1;
            int c2 = tid & 1;
            const float* wp = sm + O_WOW + c2 * PDK;
            Pre ph;
            stage_ldg(ph, h3n, CDIM, 0);
            stage_sts(ph, xs);
            __syncthreads();
            for (int ch = 0; ch < 8; ch++) {
                if (ch < 7) stage_ldg(ph, h3n, CDIM, (ch + 1) * 32);
                if (tid < 256) {
                    int k0 = ch * 32;
#pragma unroll
                    for (int k4 = 0; k4 < 8; k4++) {
                        int kk = k4 * 4;
                        F4U W; W.f = *reinterpret_cast<const float4*>(wp + k0 + kk);
                        F4U X; X.f = *reinterpret_cast<const float4*>(&xs[lr * 44 + kk]);
                        fma2(A, W.u[0], X.u[0]);
                        fma2(A, W.u[1], X.u[1]);
                    }
                }
                __syncthreads();
                if (ch < 7) { stage_sts(ph, xs); __syncthreads(); }
            }
            if (tid < 256) {
                float v = tanhf(red2(A) + sm[O_OB + c2]);
                int Row = grow0 + lr;
                int oc = s * 2 + c2;
                out[(size_t)Row * ostride + st * SUBD + oc] = v;
                __stcg(&g_prev[Row * SUBD + oc], v);
            }
        }
        group_barrier(grp, (++bar_ep) * NSLICE);
    }
}

// ---------------- launcher ----------------
extern "C" void kernel_launch(void* const* d_in, const int* in_sizes, int n_in,
                              void* d_out, int out_size) {
    const float* feat   = (const float*)d_in[0];
    const float* fd1_w  = (const float*)d_in[1];
    const float* fd1_b  = (const float*)d_in[2];
    const float* c1_w   = (const float*)d_in[3];
    const float* c1_b   = (const float*)d_in[4];
    const float* c2_w   = (const float*)d_in[5];
    const float* c2_b   = (const float*)d_in[6];
    const float* fd2_w  = (const float*)d_in[7];
    const float* fd2_b  = (const float*)d_in[8];
    const float* d1_w   = (const float*)d_in[9];
    const float* d1_b   = (const float*)d_in[10];
    const float* d2_w   = (const float*)d_in[11];
    const float* d2_b   = (const float*)d_in[12];
    const float* g1_wih = (const float*)d_in[13];
    const float* g1_whh = (const float*)d_in[14];
    const float* g1_bih = (const float*)d_in[15];
    const float* g1_bhh = (const float*)d_in[16];
    const float* g2_wih = (const float*)d_in[17];
    const float* g2_whh = (const float*)d_in[18];
    const float* g2_bih = (const float*)d_in[19];
    const float* g2_bhh = (const float*)d_in[20];
    const float* g3_wih = (const float*)d_in[21];
    const float* g3_whh = (const float*)d_in[22];
    const float* g3_bih = (const float*)d_in[23];
    const float* g3_bhh = (const float*)d_in[24];
    const float* ow     = (const float*)d_in[25];
    const float* ob     = (const float*)d_in[26];
    const int*   nbf    = (const int*)d_in[27];
    float* out = (float*)d_out;

    float *pA, *pB, *pfd1t, *pc1t, *pc2t, *pfd2t, *pH, *pPrev;
    int* pBar;
    cudaGetSymbolAddress((void**)&pA, g_bufA);
    cudaGetSymbolAddress((void**)&pB, g_bufB);
    cudaGetSymbolAddress((void**)&pfd1t, g_fd1t);
    cudaGetSymbolAddress((void**)&pc1t, g_c1t);
    cudaGetSymbolAddress((void**)&pc2t, g_c2t);
    cudaGetSymbolAddress((void**)&pfd2t, g_fd2t);
    cudaGetSymbolAddress((void**)&pH, g_h);
    cudaGetSymbolAddress((void**)&pPrev, g_prev);
    cudaGetSymbolAddress((void**)&pBar, g_bar);

    cudaMemsetAsync(pH, 0, 2 * 3 * BATCH * CDIM * sizeof(float));
    cudaMemsetAsync(pPrev, 0, BATCH * SUBD * sizeof(float));
    cudaMemsetAsync(pBar, 0, NGRP * sizeof(int));

    auto T = [](const float* src, float* dst, int N, int K) {
        int n = N * K;
        transpose_k<<<(n + 255) / 256, 256>>>(src, dst, N, K);
    };
    T(fd1_w, pfd1t, CDIM, NFEAT);
    T(c1_w,  pc1t,  CDIM, 768);
    T(c2_w,  pc2t,  CDIM, 768);
    T(fd2_w, pfd2t, CDIM, CDIM);

    // cond net
    fd1_kernel<<<BATCH * TFEAT, 256>>>(feat, fd1_b);
    conv_kernel<3><<<dim3(13, BATCH), 256>>>(pA, pc1t, c1_b, pB, 204, 202);
    conv_kernel<3><<<dim3(13, BATCH), 256>>>(pB, pc2t, c2_b, pA, 202, 200);
    conv_kernel<1><<<dim3(13, BATCH), 256>>>(pA, pfd2t, fd2_b, pB, 200, 200);

    // persistent autoregressive decoder
    cudaFuncSetAttribute(ar_kernel, cudaFuncAttributeMaxDynamicSharedMemorySize, SM_BYTES);
    ar_kernel<<<NCTA, NTHR, SM_BYTES>>>(
        d1_w, d1_b, d2_w, d2_b,
        g1_wih, g1_whh, g1_bih, g1_bhh,
        g2_wih, g2_whh, g2_bih, g2_bhh,
        g3_wih, g3_whh, g3_bih, g3_bhh,
        ow, ob, nbf, out);
}

// round 5
// speedup vs baseline: 2.0490x; 1.2472x over previous
#include <cuda_runtime.h>
#include <math.h>

typedef unsigned long long ull;

#define BATCH 512
#define TFEAT 204
#define NFEAT 20
#define CDIM  256
#define SUBD  40
#define NSLICE 32
#define NGRP   4
#define GROWS  128
#define NCTA   128
#define NTHR   256
#define KCH    32
#define XSTR   36

// ---------------- device globals ----------------
__device__ float g_bufA[BATCH * TFEAT * CDIM];   // fd1 out, later CP [b][200][256]
__device__ float g_bufB[BATCH * TFEAT * CDIM];   // cond [b][200][256]

__device__ float g_fd1t[NFEAT * CDIM];
__device__ float g_c1t[768 * CDIM];
__device__ float g_c2t[768 * CDIM];
__device__ float g_fd2t[CDIM * CDIM];
__device__ float g_d1t[CDIM * CDIM];             // transposed first-256-k of d1_w

__device__ float g_t1[BATCH * CDIM];
__device__ float g_t2[BATCH * CDIM];

// zeroed state: h ping-pong(6 planes) + prev + barrier counters, one memset
#define STATE_H     0
#define STATE_PREV  (6 * BATCH * CDIM)
#define STATE_BAR   (STATE_PREV + BATCH * SUBD)
__device__ float g_state[STATE_BAR + NGRP];
#define G_H(p, l)   (g_state + ((p) * 3 + (l)) * (BATCH * CDIM))
#define G_PREV      (g_state + STATE_PREV)
#define G_BAR       ((int*)(g_state + STATE_BAR))

// ---------------- smem layout for AR (floats) ----------------
#define PDK 260
#define O_WD2  0
#define O_GRU0 2080
#define GRU_STRIDE 12480
#define O_WOW  (O_GRU0 + 3 * GRU_STRIDE)  // 39520
#define O_D1P  (O_WOW + 520)              // 40040, [8][44]
#define O_BD2  (O_D1P + 352)
#define O_BI0  (O_BD2 + 8)
#define O_OB   (O_BI0 + 144)
#define O_XS   40548
#define O_HS   (O_XS + 4608)
#define SM_FLOATS (O_HS + 4608)           // 49764
#define SM_BYTES  (SM_FLOATS * 4)

// ---------------- f32x2 helpers ----------------
__device__ __forceinline__ void fma2(ull& d, ull a, ull b) {
    asm("fma.rn.f32x2 %0, %1, %2, %0;" : "+l"(d) : "l"(a), "l"(b));
}
__device__ __forceinline__ float red2(ull v) {
    union { ull u; float2 f; } t; t.u = v;
    return t.f.x + t.f.y;
}
__device__ __forceinline__ ull dup2(float v) {
    ull r; asm("mov.b64 %0, {%1, %1};" : "=l"(r) : "f"(v)); return r;
}
union F4U { float4 f; ull u[2]; };

__device__ __forceinline__ float sigf(float v) { return 1.f / (1.f + expf(-v)); }

// ---------------- transpose_all (one launch) ----------------
#define TS0 (CDIM * NFEAT)
#define TS1 (CDIM * 768)
#define TS2 (CDIM * 768)
#define TS3 (CDIM * CDIM)
#define TS4 (CDIM * CDIM)
#define TTOT (TS0 + TS1 + TS2 + TS3 + TS4)
__global__ void transpose_all(const float* __restrict__ fd1_w, const float* __restrict__ c1_w,
                              const float* __restrict__ c2_w, const float* __restrict__ fd2_w,
                              const float* __restrict__ d1_w) {
    int idx = blockIdx.x * 256 + threadIdx.x;
    if (idx < TS0) { int n = idx / NFEAT, k = idx % NFEAT; g_fd1t[k * CDIM + n] = fd1_w[idx]; return; }
    idx -= TS0;
    if (idx < TS1) { int n = idx / 768, k = idx % 768; g_c1t[k * CDIM + n] = c1_w[idx]; return; }
    idx -= TS1;
    if (idx < TS2) { int n = idx / 768, k = idx % 768; g_c2t[k * CDIM + n] = c2_w[idx]; return; }
    idx -= TS2;
    if (idx < TS3) { int n = idx / CDIM, k = idx % CDIM; g_fd2t[k * CDIM + n] = fd2_w[idx]; return; }
    idx -= TS3;
    if (idx < TS4) { int j = idx / CDIM, k = idx % CDIM; g_d1t[k * CDIM + j] = d1_w[j * 296 + k]; }
}

// ---------------- fd1 ----------------
__global__ void fd1_kernel(const float* __restrict__ feat, const float* __restrict__ bias) {
    __shared__ float fs[NFEAT];
    int row = blockIdx.x;
    int tid = threadIdx.x;
    if (tid < NFEAT) fs[tid] = feat[row * NFEAT + tid];
    __syncthreads();
    float acc = bias[tid];
#pragma unroll
    for (int k = 0; k < NFEAT; k++)
        acc += g_fd1t[k * CDIM + tid] * fs[k];
    g_bufA[row * CDIM + tid] = tanhf(acc);
}

// ---------------- fused conv1+conv2+fc ----------------
#define CPAD 260
__global__ void __launch_bounds__(256, 1) cond_fused(
    const float* __restrict__ c1b, const float* __restrict__ c2b,
    const float* __restrict__ fcb) {
    extern __shared__ float smf[];
    float* s_in = smf;                  // [22][260]
    float* s_m1 = smf + 22 * CPAD;      // [18][260]
    float* s_m2 = smf + 40 * CPAD;      // [16][260]

    int b = blockIdx.y;
    int t0 = blockIdx.x * 16;
    int tid = threadIdx.x;

#pragma unroll
    for (int r = 0; r < 22; r++) {
        int t = t0 + r;
        s_in[r * CPAD + tid] = (t < TFEAT) ? g_bufA[((size_t)b * TFEAT + t) * CDIM + tid] : 0.f;
    }
    __syncthreads();

    int tg = tid & 3;
    int c0 = (tid >> 2) * 4;

    // conv1: rows r = tg + 4a, a<5 (rows 0..19; only r<18 stored)
    {
        ull acc[5][2];
#pragma unroll
        for (int a = 0; a < 5; a++) { acc[a][0] = 0ull; acc[a][1] = 0ull; }
#pragma unroll 2
        for (int i = 0; i < CDIM; i++) {
#pragma unroll
            for (int j = 0; j < 3; j++) {
                F4U w; w.f = *reinterpret_cast<const float4*>(&g_c1t[(i * 3 + j) * CDIM + c0]);
#pragma unroll
                for (int a = 0; a < 5; a++) {
                    ull x2 = dup2(s_in[(tg + 4 * a + j) * CPAD + i]);
                    fma2(acc[a][0], w.u[0], x2);
                    fma2(acc[a][1], w.u[1], x2);
                }
            }
        }
        float4 bv = *reinterpret_cast<const float4*>(&c1b[c0]);
#pragma unroll
        for (int a = 0; a < 5; a++) {
            int r = tg + 4 * a;
            if (r < 18) {
                union { ull u; float2 f; } lo, hi;
                lo.u = acc[a][0]; hi.u = acc[a][1];
                float4 o;
                o.x = tanhf(lo.f.x + bv.x); o.y = tanhf(lo.f.y + bv.y);
                o.z = tanhf(hi.f.x + bv.z); o.w = tanhf(hi.f.y + bv.w);
                *reinterpret_cast<float4*>(&s_m1[r * CPAD + c0]) = o;
            }
        }
    }
    __syncthreads();

    // conv2: rows r = tg + 4a, a<4 → s_m2
    {
        ull acc[4][2];
#pragma unroll
        for (int a = 0; a < 4; a++) { acc[a][0] = 0ull; acc[a][1] = 0ull; }
#pragma unroll 2
        for (int i = 0; i < CDIM; i++) {
#pragma unroll
            for (int j = 0; j < 3; j++) {
                F4U w; w.f = *reinterpret_cast<const float4*>(&g_c2t[(i * 3 + j) * CDIM + c0]);
#pragma unroll
                for (int a = 0; a < 4; a++) {
                    ull x2 = dup2(s_m1[(tg + 4 * a + j) * CPAD + i]);
                    fma2(acc[a][0], w.u[0], x2);
                    fma2(acc[a][1], w.u[1], x2);
                }
            }
        }
        float4 bv = *reinterpret_cast<const float4*>(&c2b[c0]);
#pragma unroll
        for (int a = 0; a < 4; a++) {
            int r = tg + 4 * a;
            union { ull u; float2 f; } lo, hi;
            lo.u = acc[a][0]; hi.u = acc[a][1];
            float4 o;
            o.x = tanhf(lo.f.x + bv.x); o.y = tanhf(lo.f.y + bv.y);
            o.z = tanhf(hi.f.x + bv.z); o.w = tanhf(hi.f.y + bv.w);
            *reinterpret_cast<float4*>(&s_m2[r * CPAD + c0]) = o;
        }
    }
    __syncthreads();

    // fc: rows r = tg + 4a → cond out [b][200][256]
    {
        ull acc[4][2];
#pragma unroll
        for (int a = 0; a < 4; a++) { acc[a][0] = 0ull; acc[a][1] = 0ull; }
#pragma unroll 2
        for (int k = 0; k < CDIM; k++) {
            F4U w; w.f = *reinterpret_cast<const float4*>(&g_fd2t[k * CDIM + c0]);
#pragma unroll
            for (int a = 0; a < 4; a++) {
                ull x2 = dup2(s_m2[(tg + 4 * a) * CPAD + k]);
                fma2(acc[a][0], w.u[0], x2);
                fma2(acc[a][1], w.u[1], x2);
            }
        }
        float4 bv = *reinterpret_cast<const float4*>(&fcb[c0]);
#pragma unroll
        for (int a = 0; a < 4; a++) {
            int r = tg + 4 * a;
            int t = t0 + r;
            if (t < 200) {
                union { ull u; float2 f; } lo, hi;
                lo.u = acc[a][0]; hi.u = acc[a][1];
                float4 o;
                o.x = tanhf(lo.f.x + bv.x); o.y = tanhf(lo.f.y + bv.y);
                o.z = tanhf(hi.f.x + bv.z); o.w = tanhf(hi.f.y + bv.w);
                *reinterpret_cast<float4*>(&g_bufB[((size_t)b * 200 + t) * CDIM + c0]) = o;
            }
        }
    }
}

// ---------------- CP = cond @ d1_w[:, :256]^T + d1_b  ->  g_bufA [b][200][256] ----------------
__global__ void __launch_bounds__(256, 1) cp_kernel(const float* __restrict__ d1b) {
    __shared__ float s_c[16 * CPAD];
    int b = blockIdx.y;
    int t0 = blockIdx.x * 16;
    int tid = threadIdx.x;

#pragma unroll
    for (int r = 0; r < 16; r++) {
        int t = t0 + r;
        s_c[r * CPAD + tid] = (t < 200) ? g_bufB[((size_t)b * 200 + t) * CDIM + tid] : 0.f;
    }
    __syncthreads();

    int tg = tid & 3;
    int c0 = (tid >> 2) * 4;
    ull acc[4][2];
#pragma unroll
    for (int a = 0; a < 4; a++) { acc[a][0] = 0ull; acc[a][1] = 0ull; }
#pragma unroll 2
    for (int k = 0; k < CDIM; k++) {
        F4U w; w.f = *reinterpret_cast<const float4*>(&g_d1t[k * CDIM + c0]);
#pragma unroll
        for (int a = 0; a < 4; a++) {
            ull x2 = dup2(s_c[(tg + 4 * a) * CPAD + k]);
            fma2(acc[a][0], w.u[0], x2);
            fma2(acc[a][1], w.u[1], x2);
        }
    }
    float4 bv = *reinterpret_cast<const float4*>(&d1b[c0]);
#pragma unroll
    for (int a = 0; a < 4; a++) {
        int t = t0 + tg + 4 * a;
        if (t < 200) {
            union { ull u; float2 f; } lo, hi;
            lo.u = acc[a][0]; hi.u = acc[a][1];
            float4 o;
            o.x = lo.f.x + bv.x; o.y = lo.f.y + bv.y;
            o.z = hi.f.x + bv.z; o.w = hi.f.y + bv.w;
            *reinterpret_cast<float4*>(&g_bufA[((size_t)b * 200 + t) * CDIM + c0]) = o;
        }
    }
}

// ---------------- group barrier: release atomic + acquire poll ----------------
__device__ __forceinline__ void group_barrier(int grp, int target) {
    __syncthreads();
    if (threadIdx.x == 0) {
        int* addr = &G_BAR[grp];
        int old;
        asm volatile("atom.add.release.gpu.global.s32 %0, [%1], 1;"
                     : "=r"(old) : "l"(addr) : "memory");
        int v;
        do {
            asm volatile("ld.acquire.gpu.global.s32 %0, [%1];"
                         : "=r"(v) : "l"(addr) : "memory");
        } while (v < target);
    }
    __syncthreads();
}

// ---------------- cooperative staging: 128 rows x 32-k chunk ----------------
struct Pre4 { float4 v[4]; };

__device__ __forceinline__ void ld4(Pre4& p, const float* __restrict__ base, int k0) {
#pragma unroll
    for (int i = 0; i < 4; i++) {
        int lin = threadIdx.x + i * NTHR;
        int row = lin >> 3, f4 = lin & 7;
        p.v[i] = __ldcg(reinterpret_cast<const float4*>(base + (size_t)row * CDIM + k0 + f4 * 4));
    }
}
__device__ __forceinline__ void st4(const Pre4& p, float* buf) {
#pragma unroll
    for (int i = 0; i < 4; i++) {
        int lin = threadIdx.x + i * NTHR;
        int row = lin >> 3, f4 = lin & 7;
        *reinterpret_cast<float4*>(buf + row * XSTR + f4 * 4) = p.v[i];
    }
}

// ---------------- persistent AR kernel: 4 groups x 32 slices, 256 thr ----------------
__global__ void __launch_bounds__(NTHR, 1) ar_kernel(
    const float* __restrict__ d1_w, const float* __restrict__ d2_w, const float* __restrict__ d2b,
    const float* __restrict__ w1i, const float* __restrict__ w1h,
    const float* __restrict__ b1i, const float* __restrict__ b1h,
    const float* __restrict__ w2i, const float* __restrict__ w2h,
    const float* __restrict__ b2i, const float* __restrict__ b2h,
    const float* __restrict__ w3i, const float* __restrict__ w3h,
    const float* __restrict__ b3i, const float* __restrict__ b3h,
    const float* __restrict__ ow,  const float* __restrict__ ob,
    const int* __restrict__ nbf,   float* __restrict__ out) {
    extern __shared__ float sm[];
    int tid = threadIdx.x;
    int s = blockIdx.x & (NSLICE - 1);
    int grp = blockIdx.x >> 5;
    int grow0 = grp * GROWS;

    // ---- resident weights ----
    for (int e = tid; e < 8 * CDIM; e += NTHR) {
        int r = e >> 8, k = e & 255;
        sm[O_WD2 + r * PDK + k] = d2_w[(s * 8 + r) * CDIM + k];
    }
    const float* wis[3] = {w1i, w2i, w3i};
    const float* whs[3] = {w1h, w2h, w3h};
    const float* bis[3] = {b1i, b2i, b3i};
    const float* bhs[3] = {b1h, b2h, b3h};
    for (int l = 0; l < 3; l++) {
        for (int e = tid; e < 24 * CDIM; e += NTHR) {
            int gr = e >> 8, k = e & 255;
            int g = gr >> 3, r = gr & 7;
            sm[O_GRU0 + l * GRU_STRIDE + gr * PDK + k] = wis[l][(g * CDIM + s * 8 + r) * CDIM + k];
            sm[O_GRU0 + l * GRU_STRIDE + 3 * 8 * PDK + gr * PDK + k] =
                whs[l][(g * CDIM + s * 8 + r) * CDIM + k];
        }
        if (tid < 24) {
            int g = tid >> 3, r = tid & 7;
            sm[O_BI0 + l * 48 + tid] = bis[l][g * CDIM + s * 8 + r];
            sm[O_BI0 + l * 48 + 24 + tid] = bhs[l][g * CDIM + s * 8 + r];
        }
    }
    if (s < 20) {
        for (int e = tid; e < 2 * CDIM; e += NTHR) {
            int r = e >> 8, k = e & 255;
            sm[O_WOW + r * PDK + k] = ow[(s * 2 + r) * CDIM + k];
        }
        if (tid < 2) sm[O_OB + tid] = ob[s * 2 + tid];
    }
    for (int e = tid; e < 8 * SUBD; e += NTHR) {
        int r = e / SUBD, q = e - r * SUBD;
        sm[O_D1P + r * 44 + q] = d1_w[(s * 8 + r) * 296 + 256 + q];
    }
    if (tid < 8) sm[O_BD2 + tid] = d2b[s * 8 + tid];
    __syncthreads();

    int c = tid & 7;
    int rq = tid >> 3;               // 0..31; rows rq + 32*i
    int scol = s * 8 + c;
    int ch_hold = scol >> 5;
    int kk_hold = scol & 31;

    float* xs = sm + O_XS;
    float* hs = sm + O_HS;

    int steps = nbf[0] * 4;
    int ostride = steps * SUBD;
    int bar_ep = 0;

    const float* CP = g_bufA;        // [b][200][256], bias included
    float* t1g = g_t1 + (size_t)grow0 * CDIM;
    float* t2g = g_t2 + (size_t)grow0 * CDIM;
    float* pvg = G_PREV + (size_t)grow0 * SUBD;

    for (int st = 0; st < steps; st++) {
        int f = st >> 2;
        int p = st & 1;
        const float* h1o = G_H(p, 0) + (size_t)grow0 * CDIM;
        float*       h1n = G_H(p ^ 1, 0) + (size_t)grow0 * CDIM;
        const float* h2o = G_H(p, 1) + (size_t)grow0 * CDIM;
        float*       h2n = G_H(p ^ 1, 1) + (size_t)grow0 * CDIM;
        const float* h3o = G_H(p, 2) + (size_t)grow0 * CDIM;
        float*       h3n = G_H(p ^ 1, 2) + (size_t)grow0 * CDIM;

        // ========== d1: tanh(CP + prev @ Wp^T) ==========
        {
            // stage prev [128][40] into xs region (stride 44, spans into hs: 5632 <= 9216)
#pragma unroll
            for (int i = 0; i < 5; i++) {
                int lin = tid + i * NTHR;
                int row = lin / 10, f4 = lin - row * 10;
                *reinterpret_cast<float4*>(&xs[row * 44 + f4 * 4]) =
                    __ldcg(reinterpret_cast<const float4*>(&pvg[row * SUBD + f4 * 4]));
            }
            float cpv[4];
#pragma unroll
            for (int i = 0; i < 4; i++) {
                int row = grow0 + rq + 32 * i;
                cpv[i] = __ldcg(&CP[((size_t)row * 200 + f) * CDIM + scol]);
            }
            __syncthreads();
            ull A[4] = {0, 0, 0, 0};
            const float* wp = sm + O_D1P + c * 44;
#pragma unroll
            for (int k4 = 0; k4 < 10; k4++) {
                F4U W; W.f = *reinterpret_cast<const float4*>(wp + k4 * 4);
#pragma unroll
                for (int i = 0; i < 4; i++) {
                    F4U X; X.f = *reinterpret_cast<const float4*>(&xs[(rq + 32 * i) * 44 + k4 * 4]);
                    fma2(A[i], W.u[0], X.u[0]);
                    fma2(A[i], W.u[1], X.u[1]);
                }
            }
#pragma unroll
            for (int i = 0; i < 4; i++)
                __stcg(&t1g[(rq + 32 * i) * CDIM + scol], tanhf(red2(A[i]) + cpv[i]));
        }
        group_barrier(grp, (++bar_ep) * NSLICE);

        // ========== d2 ==========
        {
            ull A[4] = {0, 0, 0, 0};
            const float* wp = sm + O_WD2 + c * PDK;
            Pre4 px;
            ld4(px, t1g, 0);
            st4(px, xs);
            __syncthreads();
            for (int ch = 0; ch < 8; ch++) {
                if (ch < 7) ld4(px, t1g, (ch + 1) * KCH);
                int k0 = ch * KCH;
#pragma unroll
                for (int k4 = 0; k4 < 8; k4++) {
                    F4U W; W.f = *reinterpret_cast<const float4*>(wp + k0 + k4 * 4);
#pragma unroll
                    for (int i = 0; i < 4; i++) {
                        F4U X; X.f = *reinterpret_cast<const float4*>(&xs[(rq + 32 * i) * XSTR + k4 * 4]);
                        fma2(A[i], W.u[0], X.u[0]);
                        fma2(A[i], W.u[1], X.u[1]);
                    }
                }
                __syncthreads();
                if (ch < 7) { st4(px, xs); __syncthreads(); }
            }
            float bb = sm[O_BD2 + c];
#pragma unroll
            for (int i = 0; i < 4; i++)
                __stcg(&t2g[(rq + 32 * i) * CDIM + scol], tanhf(red2(A[i]) + bb));
        }
        group_barrier(grp, (++bar_ep) * NSLICE);

        // ========== 3 GRU layers ==========
        const float* xsrcs[3] = {t2g, h1n, h2n};
        const float* hsrcs[3] = {h1o, h2o, h3o};
        float*       hdsts[3] = {h1n, h2n, h3n};
        for (int gl = 0; gl < 3; gl++) {
            const float* xsrc = xsrcs[gl];
            const float* hsrc = hsrcs[gl];
            float*       hdst = hdsts[gl];

            const float* wb = sm + O_GRU0 + gl * GRU_STRIDE;
            const float* wr = wb + (0 * 8 + c) * PDK;
            const float* wz = wb + (1 * 8 + c) * PDK;
            const float* wn = wb + (2 * 8 + c) * PDK;
            const float* vr = wb + 3 * 8 * PDK + (0 * 8 + c) * PDK;
            const float* vz = wb + 3 * 8 * PDK + (1 * 8 + c) * PDK;
            const float* vn = wb + 3 * 8 * PDK + (2 * 8 + c) * PDK;

            ull Ar[4] = {0,0,0,0}, Az[4] = {0,0,0,0}, An[4] = {0,0,0,0};
            ull Br[4] = {0,0,0,0}, Bz[4] = {0,0,0,0}, Bn[4] = {0,0,0,0};
            float hold[4];

            Pre4 px, ph;
            ld4(px, xsrc, 0);
            ld4(ph, hsrc, 0);
            st4(px, xs);
            st4(ph, hs);
            __syncthreads();
            for (int ch = 0; ch < 8; ch++) {
                if (ch < 7) {
                    ld4(px, xsrc, (ch + 1) * KCH);
                    ld4(ph, hsrc, (ch + 1) * KCH);
                }
                int k0 = ch * KCH;
#pragma unroll
                for (int k4 = 0; k4 < 8; k4++) {
                    int gk = k0 + k4 * 4;
                    F4U Wr; Wr.f = *reinterpret_cast<const float4*>(wr + gk);
                    F4U Wz; Wz.f = *reinterpret_cast<const float4*>(wz + gk);
                    F4U Wn; Wn.f = *reinterpret_cast<const float4*>(wn + gk);
                    F4U Vr; Vr.f = *reinterpret_cast<const float4*>(vr + gk);
                    F4U Vz; Vz.f = *reinterpret_cast<const float4*>(vz + gk);
                    F4U Vn; Vn.f = *reinterpret_cast<const float4*>(vn + gk);
#pragma unroll
                    for (int i = 0; i < 4; i++) {
                        F4U X; X.f = *reinterpret_cast<const float4*>(&xs[(rq + 32 * i) * XSTR + k4 * 4]);
                        F4U H; H.f = *reinterpret_cast<const float4*>(&hs[(rq + 32 * i) * XSTR + k4 * 4]);
                        fma2(Ar[i], Wr.u[0], X.u[0]); fma2(Ar[i], Wr.u[1], X.u[1]);
                        fma2(Az[i], Wz.u[0], X.u[0]); fma2(Az[i], Wz.u[1], X.u[1]);
                        fma2(An[i], Wn.u[0], X.u[0]); fma2(An[i], Wn.u[1], X.u[1]);
                        fma2(Br[i], Vr.u[0], H.u[0]); fma2(Br[i], Vr.u[1], H.u[1]);
                        fma2(Bz[i], Vz.u[0], H.u[0]); fma2(Bz[i], Vz.u[1], H.u[1]);
                        fma2(Bn[i], Vn.u[0], H.u[0]); fma2(Bn[i], Vn.u[1], H.u[1]);
                    }
                }
                if (ch == ch_hold) {
#pragma unroll
                    for (int i = 0; i < 4; i++)
                        hold[i] = hs[(rq + 32 * i) * XSTR + kk_hold];
                }
                __syncthreads();
                if (ch < 7) {
                    st4(px, xs);
                    st4(ph, hs);
                    __syncthreads();
                }
            }
            const float* bi = sm + O_BI0 + gl * 48;
            const float* bh = bi + 24;
            float bir = bi[c], biz = bi[8 + c], bin = bi[16 + c];
            float bhr = bh[c], bhz = bh[8 + c], bhn = bh[16 + c];
#pragma unroll
            for (int i = 0; i < 4; i++) {
                float r = sigf(red2(Ar[i]) + bir + red2(Br[i]) + bhr);
                float z = sigf(red2(Az[i]) + biz + red2(Bz[i]) + bhz);
                float n = tanhf(red2(An[i]) + bin + r * (red2(Bn[i]) + bhn));
                __stcg(&hdst[(rq + 32 * i) * CDIM + scol], (1.f - z) * n + z * hold[i]);
            }
            group_barrier(grp, (++bar_ep) * NSLICE);
        }

        // ========== output layer (slices 0..19: 2 cols x 128 rows) ==========
        if (s < 20) {
            int lr = tid >> 1;
            int c2 = tid & 1;
            ull A = 0ull;
            const float* wp = sm + O_WOW + c2 * PDK;
            Pre4 ph;
            ld4(ph, h3n, 0);
            st4(ph, xs);
            __syncthreads();
            for (int ch = 0; ch < 8; ch++) {
                if (ch < 7) ld4(ph, h3n, (ch + 1) * KCH);
                int k0 = ch * KCH;
#pragma unroll
                for (int k4 = 0; k4 < 8; k4++) {
                    F4U W; W.f = *reinterpret_cast<const float4*>(wp + k0 + k4 * 4);
                    F4U X; X.f = *reinterpret_cast<const float4*>(&xs[lr * XSTR + k4 * 4]);
                    fma2(A, W.u[0], X.u[0]);
                    fma2(A, W.u[1], X.u[1]);
                }
                __syncthreads();
                if (ch < 7) { st4(ph, xs); __syncthreads(); }
            }
            float v = tanhf(red2(A) + sm[O_OB + c2]);
            int Row = grow0 + lr;
            int oc = s * 2 + c2;
            out[(size_t)Row * ostride + st * SUBD + oc] = v;
            __stcg(&pvg[lr * SUBD + oc], v);
        }
        group_barrier(grp, (++bar_ep) * NSLICE);
    }
}

// ---------------- launcher ----------------
extern "C" void kernel_launch(void* const* d_in, const int* in_sizes, int n_in,
                              void* d_out, int out_size) {
    const float* feat   = (const float*)d_in[0];
    const float* fd1_w  = (const float*)d_in[1];
    const float* fd1_b  = (const float*)d_in[2];
    const float* c1_w   = (const float*)d_in[3];
    const float* c1_b   = (const float*)d_in[4];
    const float* c2_w   = (const float*)d_in[5];
    const float* c2_b   = (const float*)d_in[6];
    const float* fd2_w  = (const float*)d_in[7];
    const float* fd2_b  = (const float*)d_in[8];
    const float* d1_w   = (const float*)d_in[9];
    const float* d1_b   = (const float*)d_in[10];
    const float* d2_w   = (const float*)d_in[11];
    const float* d2_b   = (const float*)d_in[12];
    const float* g1_wih = (const float*)d_in[13];
    const float* g1_whh = (const float*)d_in[14];
    const float* g1_bih = (const float*)d_in[15];
    const float* g1_bhh = (const float*)d_in[16];
    const float* g2_wih = (const float*)d_in[17];
    const float* g2_whh = (const float*)d_in[18];
    const float* g2_bih = (const float*)d_in[19];
    const float* g2_bhh = (const float*)d_in[20];
    const float* g3_wih = (const float*)d_in[21];
    const float* g3_whh = (const float*)d_in[22];
    const float* g3_bih = (const float*)d_in[23];
    const float* g3_bhh = (const float*)d_in[24];
    const float* ow     = (const float*)d_in[25];
    const float* ob     = (const float*)d_in[26];
    const int*   nbf    = (const int*)d_in[27];
    float* out = (float*)d_out;

    float* pState;
    cudaGetSymbolAddress((void**)&pState, g_state);

    // launch 1: one memset for h/prev/bar
    cudaMemsetAsync(pState, 0, (STATE_BAR + NGRP) * sizeof(float));
    // launch 2: all weight transposes
    transpose_all<<<(TTOT + 255) / 256, 256>>>(fd1_w, c1_w, c2_w, fd2_w, d1_w);
    // launch 3: fd1
    fd1_kernel<<<BATCH * TFEAT, 256>>>(feat, fd1_b);
    // launch 4: fused conv1+conv2+fc
    static bool attr_set = false;
    if (!attr_set) {
        cudaFuncSetAttribute(cond_fused, cudaFuncAttributeMaxDynamicSharedMemorySize,
                             56 * CPAD * 4);
        cudaFuncSetAttribute(ar_kernel, cudaFuncAttributeMaxDynamicSharedMemorySize, SM_BYTES);
        attr_set = true;
    }
    cond_fused<<<dim3(13, BATCH), 256, 56 * CPAD * 4>>>(c1_b, c2_b, fd2_b);
    // launch 5: CP precompute
    cp_kernel<<<dim3(13, BATCH), 256>>>(d1_b);
    // launch 6: persistent AR decoder (ncu capture slot)
    ar_kernel<<<NCTA, NTHR, SM_BYTES>>>(
        d1_w, d2_w, d2_b,
        g1_wih, g1_whh, g1_bih, g1_bhh,
        g2_wih, g2_whh, g2_bih, g2_bhh,
        g3_wih, g3_whh, g3_bih, g3_bhh,
        ow, ob, nbf, out);
}

// round 6
// speedup vs baseline: 2.0854x; 1.0178x over previous
#include <cuda_runtime.h>
#include <math.h>

typedef unsigned long long ull;

#define BATCH 512
#define TFEAT 204
#define NFEAT 20
#define CDIM  256
#define SUBD  40
#define NSLICE 32
#define NGRP   4
#define GROWS  128
#define NCTA   128
#define NTHR   256
#define KCH    32
#define XSTR   36

// ---------------- device globals ----------------
__device__ float g_bufA[BATCH * TFEAT * CDIM];   // fd1 out
__device__ float g_cp[BATCH * 200 * CDIM];       // CP = cond @ d1_w[:, :256]^T + d1_b

__device__ float g_fd1t[NFEAT * CDIM];
__device__ float g_c1t[768 * CDIM];
__device__ float g_c2t[768 * CDIM];
__device__ float g_fd2t[CDIM * CDIM];
__device__ float g_d1t[CDIM * CDIM];             // transposed first-256-k of d1_w

__device__ float g_t1[BATCH * CDIM];
__device__ float g_t2[BATCH * CDIM];

// zeroed state: h ping-pong(6 planes) + prev + padded barrier counters (one memset)
#define STATE_H     0
#define STATE_PREV  (6 * BATCH * CDIM)
#define STATE_BAR   (STATE_PREV + BATCH * SUBD)
#define STATE_TOT   (STATE_BAR + NGRP * 32)
__device__ float g_state[STATE_TOT];
#define G_H(p, l)   (g_state + ((p) * 3 + (l)) * (BATCH * CDIM))
#define G_PREV      (g_state + STATE_PREV)
#define G_BAR(grp)  ((int*)(g_state + STATE_BAR) + (grp) * 32)   // 128B apart

// ---------------- smem layout for AR (floats) ----------------
#define PDK 260
#define O_WD2  0
#define O_GRU0 2080
#define GRU_STRIDE 12480
#define O_WOW  (O_GRU0 + 3 * GRU_STRIDE)  // 39520
#define O_D1P  (O_WOW + 520)              // [8][44]
#define O_BD2  (O_D1P + 352)
#define O_BI0  (O_BD2 + 8)
#define O_OB   (O_BI0 + 144)
#define O_XS   40548
#define O_HS   (O_XS + 4608)
#define SM_FLOATS (O_HS + 4608)
#define SM_BYTES  (SM_FLOATS * 4)

// ---------------- f32x2 helpers ----------------
__device__ __forceinline__ void fma2(ull& d, ull a, ull b) {
    asm("fma.rn.f32x2 %0, %1, %2, %0;" : "+l"(d) : "l"(a), "l"(b));
}
__device__ __forceinline__ float red2(ull v) {
    union { ull u; float2 f; } t; t.u = v;
    return t.f.x + t.f.y;
}
__device__ __forceinline__ ull dup2(float v) {
    ull r; asm("mov.b64 %0, {%1, %1};" : "=l"(r) : "f"(v)); return r;
}
union F4U { float4 f; ull u[2]; };

__device__ __forceinline__ float sigf(float v) { return 1.f / (1.f + expf(-v)); }

// ---------------- transpose_all (one launch) ----------------
#define TS0 (CDIM * NFEAT)
#define TS1 (CDIM * 768)
#define TS2 (CDIM * 768)
#define TS3 (CDIM * CDIM)
#define TS4 (CDIM * CDIM)
#define TTOT (TS0 + TS1 + TS2 + TS3 + TS4)
__global__ void transpose_all(const float* __restrict__ fd1_w, const float* __restrict__ c1_w,
                              const float* __restrict__ c2_w, const float* __restrict__ fd2_w,
                              const float* __restrict__ d1_w) {
    int idx = blockIdx.x * 256 + threadIdx.x;
    if (idx < TS0) { int n = idx / NFEAT, k = idx % NFEAT; g_fd1t[k * CDIM + n] = fd1_w[idx]; return; }
    idx -= TS0;
    if (idx < TS1) { int n = idx / 768, k = idx % 768; g_c1t[k * CDIM + n] = c1_w[idx]; return; }
    idx -= TS1;
    if (idx < TS2) { int n = idx / 768, k = idx % 768; g_c2t[k * CDIM + n] = c2_w[idx]; return; }
    idx -= TS2;
    if (idx < TS3) { int n = idx / CDIM, k = idx % CDIM; g_fd2t[k * CDIM + n] = fd2_w[idx]; return; }
    idx -= TS3;
    if (idx < TS4) { int j = idx / CDIM, k = idx % CDIM; g_d1t[k * CDIM + j] = d1_w[j * 296 + k]; }
}

// ---------------- fd1 ----------------
__global__ void fd1_kernel(const float* __restrict__ feat, const float* __restrict__ bias) {
    __shared__ float fs[NFEAT];
    int row = blockIdx.x;
    int tid = threadIdx.x;
    if (tid < NFEAT) fs[tid] = feat[row * NFEAT + tid];
    __syncthreads();
    float acc = bias[tid];
#pragma unroll
    for (int k = 0; k < NFEAT; k++)
        acc += g_fd1t[k * CDIM + tid] * fs[k];
    g_bufA[row * CDIM + tid] = tanhf(acc);
}

// ---------------- fused conv1+conv2+fc+CP ----------------
#define CPAD 260
__global__ void __launch_bounds__(256, 1) cond_fused(
    const float* __restrict__ c1b, const float* __restrict__ c2b,
    const float* __restrict__ fcb, const float* __restrict__ d1b) {
    extern __shared__ float smf[];
    float* s_in = smf;                  // [22][260]
    float* s_m1 = smf + 22 * CPAD;      // [18][260] (reused for fc out [16][260])
    float* s_m2 = smf + 40 * CPAD;      // [16][260]

    int b = blockIdx.y;
    int t0 = blockIdx.x * 16;
    int tid = threadIdx.x;

#pragma unroll
    for (int r = 0; r < 22; r++) {
        int t = t0 + r;
        s_in[r * CPAD + tid] = (t < TFEAT) ? g_bufA[((size_t)b * TFEAT + t) * CDIM + tid] : 0.f;
    }
    __syncthreads();

    int tg = tid & 3;
    int c0 = (tid >> 2) * 4;

    // conv1 -> s_m1 rows 0..17
    {
        ull acc[5][2];
#pragma unroll
        for (int a = 0; a < 5; a++) { acc[a][0] = 0ull; acc[a][1] = 0ull; }
#pragma unroll 2
        for (int i = 0; i < CDIM; i++) {
#pragma unroll
            for (int j = 0; j < 3; j++) {
                F4U w; w.f = *reinterpret_cast<const float4*>(&g_c1t[(i * 3 + j) * CDIM + c0]);
#pragma unroll
                for (int a = 0; a < 5; a++) {
                    ull x2 = dup2(s_in[(tg + 4 * a + j) * CPAD + i]);
                    fma2(acc[a][0], w.u[0], x2);
                    fma2(acc[a][1], w.u[1], x2);
                }
            }
        }
        float4 bv = *reinterpret_cast<const float4*>(&c1b[c0]);
#pragma unroll
        for (int a = 0; a < 5; a++) {
            int r = tg + 4 * a;
            if (r < 18) {
                union { ull u; float2 f; } lo, hi;
                lo.u = acc[a][0]; hi.u = acc[a][1];
                float4 o;
                o.x = tanhf(lo.f.x + bv.x); o.y = tanhf(lo.f.y + bv.y);
                o.z = tanhf(hi.f.x + bv.z); o.w = tanhf(hi.f.y + bv.w);
                *reinterpret_cast<float4*>(&s_m1[r * CPAD + c0]) = o;
            }
        }
    }
    __syncthreads();

    // conv2 -> s_m2 rows 0..15
    {
        ull acc[4][2];
#pragma unroll
        for (int a = 0; a < 4; a++) { acc[a][0] = 0ull; acc[a][1] = 0ull; }
#pragma unroll 2
        for (int i = 0; i < CDIM; i++) {
#pragma unroll
            for (int j = 0; j < 3; j++) {
                F4U w; w.f = *reinterpret_cast<const float4*>(&g_c2t[(i * 3 + j) * CDIM + c0]);
#pragma unroll
                for (int a = 0; a < 4; a++) {
                    ull x2 = dup2(s_m1[(tg + 4 * a + j) * CPAD + i]);
                    fma2(acc[a][0], w.u[0], x2);
                    fma2(acc[a][1], w.u[1], x2);
                }
            }
        }
        float4 bv = *reinterpret_cast<const float4*>(&c2b[c0]);
#pragma unroll
        for (int a = 0; a < 4; a++) {
            int r = tg + 4 * a;
            union { ull u; float2 f; } lo, hi;
            lo.u = acc[a][0]; hi.u = acc[a][1];
            float4 o;
            o.x = tanhf(lo.f.x + bv.x); o.y = tanhf(lo.f.y + bv.y);
            o.z = tanhf(hi.f.x + bv.z); o.w = tanhf(hi.f.y + bv.w);
            *reinterpret_cast<float4*>(&s_m2[r * CPAD + c0]) = o;
        }
    }
    __syncthreads();

    // fc: cond tile -> s_m1 rows 0..15 (smem only; cond never hits global)
    {
        ull acc[4][2];
#pragma unroll
        for (int a = 0; a < 4; a++) { acc[a][0] = 0ull; acc[a][1] = 0ull; }
#pragma unroll 2
        for (int k = 0; k < CDIM; k++) {
            F4U w; w.f = *reinterpret_cast<const float4*>(&g_fd2t[k * CDIM + c0]);
#pragma unroll
            for (int a = 0; a < 4; a++) {
                ull x2 = dup2(s_m2[(tg + 4 * a) * CPAD + k]);
                fma2(acc[a][0], w.u[0], x2);
                fma2(acc[a][1], w.u[1], x2);
            }
        }
        float4 bv = *reinterpret_cast<const float4*>(&fcb[c0]);
#pragma unroll
        for (int a = 0; a < 4; a++) {
            int r = tg + 4 * a;
            union { ull u; float2 f; } lo, hi;
            lo.u = acc[a][0]; hi.u = acc[a][1];
            float4 o;
            o.x = tanhf(lo.f.x + bv.x); o.y = tanhf(lo.f.y + bv.y);
            o.z = tanhf(hi.f.x + bv.z); o.w = tanhf(hi.f.y + bv.w);
            *reinterpret_cast<float4*>(&s_m1[r * CPAD + c0]) = o;
        }
    }
    __syncthreads();

    // CP: cond @ d1t + d1_b -> g_cp (pre-activation; no tanh)
    {
        ull acc[4][2];
#pragma unroll
        for (int a = 0; a < 4; a++) { acc[a][0] = 0ull; acc[a][1] = 0ull; }
#pragma unroll 2
        for (int k = 0; k < CDIM; k++) {
            F4U w; w.f = *reinterpret_cast<const float4*>(&g_d1t[k * CDIM + c0]);
#pragma unroll
            for (int a = 0; a < 4; a++) {
                ull x2 = dup2(s_m1[(tg + 4 * a) * CPAD + k]);
                fma2(acc[a][0], w.u[0], x2);
                fma2(acc[a][1], w.u[1], x2);
            }
        }
        float4 bv = *reinterpret_cast<const float4*>(&d1b[c0]);
#pragma unroll
        for (int a = 0; a < 4; a++) {
            int t = t0 + tg + 4 * a;
            if (t < 200) {
                union { ull u; float2 f; } lo, hi;
                lo.u = acc[a][0]; hi.u = acc[a][1];
                float4 o;
                o.x = lo.f.x + bv.x; o.y = lo.f.y + bv.y;
                o.z = hi.f.x + bv.z; o.w = hi.f.y + bv.w;
                *reinterpret_cast<float4*>(&g_cp[((size_t)b * 200 + t) * CDIM + c0]) = o;
            }
        }
    }
}

// ---------------- group barrier: red.release + acquire poll, padded counters ----------------
__device__ __forceinline__ void group_barrier(int grp, int target) {
    __syncthreads();
    if (threadIdx.x == 0) {
        int* addr = G_BAR(grp);
        asm volatile("red.release.gpu.global.add.s32 [%0], 1;"
                     :: "l"(addr) : "memory");
        int v;
        do {
            asm volatile("ld.acquire.gpu.global.s32 %0, [%1];"
                         : "=r"(v) : "l"(addr) : "memory");
        } while (v < target);
    }
    __syncthreads();
}

// ---------------- cooperative staging: 128 rows x 32-k chunk ----------------
struct Pre4 { float4 v[4]; };

__device__ __forceinline__ void ld4(Pre4& p, const float* __restrict__ base, int k0) {
#pragma unroll
    for (int i = 0; i < 4; i++) {
        int lin = threadIdx.x + i * NTHR;
        int row = lin >> 3, f4 = lin & 7;
        p.v[i] = __ldcg(reinterpret_cast<const float4*>(base + (size_t)row * CDIM + k0 + f4 * 4));
    }
}
__device__ __forceinline__ void st4(const Pre4& p, float* buf) {
#pragma unroll
    for (int i = 0; i < 4; i++) {
        int lin = threadIdx.x + i * NTHR;
        int row = lin >> 3, f4 = lin & 7;
        *reinterpret_cast<float4*>(buf + row * XSTR + f4 * 4) = p.v[i];
    }
}

// ---------------- persistent AR kernel: 4 groups x 32 slices, 256 thr ----------------
__global__ void __launch_bounds__(NTHR, 1) ar_kernel(
    const float* __restrict__ d1_w, const float* __restrict__ d2_w, const float* __restrict__ d2b,
    const float* __restrict__ w1i, const float* __restrict__ w1h,
    const float* __restrict__ b1i, const float* __restrict__ b1h,
    const float* __restrict__ w2i, const float* __restrict__ w2h,
    const float* __restrict__ b2i, const float* __restrict__ b2h,
    const float* __restrict__ w3i, const float* __restrict__ w3h,
    const float* __restrict__ b3i, const float* __restrict__ b3h,
    const float* __restrict__ ow,  const float* __restrict__ ob,
    const int* __restrict__ nbf,   float* __restrict__ out) {
    extern __shared__ float sm[];
    int tid = threadIdx.x;
    int s = blockIdx.x & (NSLICE - 1);
    int grp = blockIdx.x >> 5;
    int grow0 = grp * GROWS;

    // ---- resident weights ----
    for (int e = tid; e < 8 * CDIM; e += NTHR) {
        int r = e >> 8, k = e & 255;
        sm[O_WD2 + r * PDK + k] = d2_w[(s * 8 + r) * CDIM + k];
    }
    const float* wis[3] = {w1i, w2i, w3i};
    const float* whs[3] = {w1h, w2h, w3h};
    const float* bis[3] = {b1i, b2i, b3i};
    const float* bhs[3] = {b1h, b2h, b3h};
    for (int l = 0; l < 3; l++) {
        for (int e = tid; e < 24 * CDIM; e += NTHR) {
            int gr = e >> 8, k = e & 255;
            int g = gr >> 3, r = gr & 7;
            sm[O_GRU0 + l * GRU_STRIDE + gr * PDK + k] = wis[l][(g * CDIM + s * 8 + r) * CDIM + k];
            sm[O_GRU0 + l * GRU_STRIDE + 3 * 8 * PDK + gr * PDK + k] =
                whs[l][(g * CDIM + s * 8 + r) * CDIM + k];
        }
        if (tid < 24) {
            int g = tid >> 3, r = tid & 7;
            sm[O_BI0 + l * 48 + tid] = bis[l][g * CDIM + s * 8 + r];
            sm[O_BI0 + l * 48 + 24 + tid] = bhs[l][g * CDIM + s * 8 + r];
        }
    }
    if (s < 20) {
        for (int e = tid; e < 2 * CDIM; e += NTHR) {
            int r = e >> 8, k = e & 255;
            sm[O_WOW + r * PDK + k] = ow[(s * 2 + r) * CDIM + k];
        }
        if (tid < 2) sm[O_OB + tid] = ob[s * 2 + tid];
    }
    for (int e = tid; e < 8 * SUBD; e += NTHR) {
        int r = e / SUBD, q = e - r * SUBD;
        sm[O_D1P + r * 44 + q] = d1_w[(s * 8 + r) * 296 + 256 + q];
    }
    if (tid < 8) sm[O_BD2 + tid] = d2b[s * 8 + tid];
    __syncthreads();

    int c = tid & 7;
    int rq = tid >> 3;
    int scol = s * 8 + c;
    int ch_hold = scol >> 5;
    int kk_hold = scol & 31;

    float* xs = sm + O_XS;
    float* hs = sm + O_HS;

    int steps = nbf[0] * 4;
    int ostride = steps * SUBD;
    int bar_ep = 0;

    const float* CP = g_cp;
    float* t1g = g_t1 + (size_t)grow0 * CDIM;
    float* t2g = g_t2 + (size_t)grow0 * CDIM;
    float* pvg = G_PREV + (size_t)grow0 * SUBD;

    for (int st = 0; st < steps; st++) {
        int f = st >> 2;
        int p = st & 1;
        const float* h1o = G_H(p, 0) + (size_t)grow0 * CDIM;
        float*       h1n = G_H(p ^ 1, 0) + (size_t)grow0 * CDIM;
        const float* h2o = G_H(p, 1) + (size_t)grow0 * CDIM;
        float*       h2n = G_H(p ^ 1, 1) + (size_t)grow0 * CDIM;
        const float* h3o = G_H(p, 2) + (size_t)grow0 * CDIM;
        float*       h3n = G_H(p ^ 1, 2) + (size_t)grow0 * CDIM;

        // ========== d1: tanh(CP + prev @ Wp^T) ==========
        {
#pragma unroll
            for (int i = 0; i < 5; i++) {
                int lin = tid + i * NTHR;
                int row = lin / 10, f4 = lin - row * 10;
                *reinterpret_cast<float4*>(&xs[row * 44 + f4 * 4]) =
                    __ldcg(reinterpret_cast<const float4*>(&pvg[row * SUBD + f4 * 4]));
            }
            float cpv[4];
#pragma unroll
            for (int i = 0; i < 4; i++) {
                int row = grow0 + rq + 32 * i;
                cpv[i] = __ldcg(&CP[((size_t)row * 200 + f) * CDIM + scol]);
            }
            __syncthreads();
            ull A[4] = {0, 0, 0, 0};
            const float* wp = sm + O_D1P + c * 44;
#pragma unroll
            for (int k4 = 0; k4 < 10; k4++) {
                F4U W; W.f = *reinterpret_cast<const float4*>(wp + k4 * 4);
#pragma unroll
                for (int i = 0; i < 4; i++) {
                    F4U X; X.f = *reinterpret_cast<const float4*>(&xs[(rq + 32 * i) * 44 + k4 * 4]);
                    fma2(A[i], W.u[0], X.u[0]);
                    fma2(A[i], W.u[1], X.u[1]);
                }
            }
#pragma unroll
            for (int i = 0; i < 4; i++)
                __stcg(&t1g[(rq + 32 * i) * CDIM + scol], tanhf(red2(A[i]) + cpv[i]));
        }
        group_barrier(grp, (++bar_ep) * NSLICE);

        // ========== d2 ==========
        {
            ull A[4] = {0, 0, 0, 0};
            const float* wp = sm + O_WD2 + c * PDK;
            Pre4 px;
            ld4(px, t1g, 0);
            st4(px, xs);
            __syncthreads();
            for (int ch = 0; ch < 8; ch++) {
                if (ch < 7) ld4(px, t1g, (ch + 1) * KCH);
                int k0 = ch * KCH;
#pragma unroll
                for (int k4 = 0; k4 < 8; k4++) {
                    F4U W; W.f = *reinterpret_cast<const float4*>(wp + k0 + k4 * 4);
#pragma unroll
                    for (int i = 0; i < 4; i++) {
                        F4U X; X.f = *reinterpret_cast<const float4*>(&xs[(rq + 32 * i) * XSTR + k4 * 4]);
                        fma2(A[i], W.u[0], X.u[0]);
                        fma2(A[i], W.u[1], X.u[1]);
                    }
                }
                __syncthreads();
                if (ch < 7) { st4(px, xs); __syncthreads(); }
            }
            float bb = sm[O_BD2 + c];
#pragma unroll
            for (int i = 0; i < 4; i++)
                __stcg(&t2g[(rq + 32 * i) * CDIM + scol], tanhf(red2(A[i]) + bb));
        }
        group_barrier(grp, (++bar_ep) * NSLICE);

        // ========== 3 GRU layers ==========
        const float* xsrcs[3] = {t2g, h1n, h2n};
        const float* hsrcs[3] = {h1o, h2o, h3o};
        float*       hdsts[3] = {h1n, h2n, h3n};
        for (int gl = 0; gl < 3; gl++) {
            const float* xsrc = xsrcs[gl];
            const float* hsrc = hsrcs[gl];
            float*       hdst = hdsts[gl];

            const float* wb = sm + O_GRU0 + gl * GRU_STRIDE;
            const float* wr = wb + (0 * 8 + c) * PDK;
            const float* wz = wb + (1 * 8 + c) * PDK;
            const float* wn = wb + (2 * 8 + c) * PDK;
            const float* vr = wb + 3 * 8 * PDK + (0 * 8 + c) * PDK;
            const float* vz = wb + 3 * 8 * PDK + (1 * 8 + c) * PDK;
            const float* vn = wb + 3 * 8 * PDK + (2 * 8 + c) * PDK;

            ull Ar[4] = {0,0,0,0}, Az[4] = {0,0,0,0}, An[4] = {0,0,0,0};
            ull Br[4] = {0,0,0,0}, Bz[4] = {0,0,0,0}, Bn[4] = {0,0,0,0};
            float hold[4];

            Pre4 px, ph;
            ld4(px, xsrc, 0);
            ld4(ph, hsrc, 0);
            st4(px, xs);
            st4(ph, hs);
            __syncthreads();
            for (int ch = 0; ch < 8; ch++) {
                if (ch < 7) {
                    ld4(px, xsrc, (ch + 1) * KCH);
                    ld4(ph, hsrc, (ch + 1) * KCH);
                }
                int k0 = ch * KCH;
#pragma unroll
                for (int k4 = 0; k4 < 8; k4++) {
                    int gk = k0 + k4 * 4;
                    F4U Wr; Wr.f = *reinterpret_cast<const float4*>(wr + gk);
                    F4U Wz; Wz.f = *reinterpret_cast<const float4*>(wz + gk);
                    F4U Wn; Wn.f = *reinterpret_cast<const float4*>(wn + gk);
                    F4U Vr; Vr.f = *reinterpret_cast<const float4*>(vr + gk);
                    F4U Vz; Vz.f = *reinterpret_cast<const float4*>(vz + gk);
                    F4U Vn; Vn.f = *reinterpret_cast<const float4*>(vn + gk);
#pragma unroll
                    for (int i = 0; i < 4; i++) {
                        F4U X; X.f = *reinterpret_cast<const float4*>(&xs[(rq + 32 * i) * XSTR + k4 * 4]);
                        F4U H; H.f = *reinterpret_cast<const float4*>(&hs[(rq + 32 * i) * XSTR + k4 * 4]);
                        fma2(Ar[i], Wr.u[0], X.u[0]); fma2(Ar[i], Wr.u[1], X.u[1]);
                        fma2(Az[i], Wz.u[0], X.u[0]); fma2(Az[i], Wz.u[1], X.u[1]);
                        fma2(An[i], Wn.u[0], X.u[0]); fma2(An[i], Wn.u[1], X.u[1]);
                        fma2(Br[i], Vr.u[0], H.u[0]); fma2(Br[i], Vr.u[1], H.u[1]);
                        fma2(Bz[i], Vz.u[0], H.u[0]); fma2(Bz[i], Vz.u[1], H.u[1]);
                        fma2(Bn[i], Vn.u[0], H.u[0]); fma2(Bn[i], Vn.u[1], H.u[1]);
                    }
                }
                if (ch == ch_hold) {
#pragma unroll
                    for (int i = 0; i < 4; i++)
                        hold[i] = hs[(rq + 32 * i) * XSTR + kk_hold];
                }
                __syncthreads();
                if (ch < 7) {
                    st4(px, xs);
                    st4(ph, hs);
                    __syncthreads();
                }
            }
            const float* bi = sm + O_BI0 + gl * 48;
            const float* bh = bi + 24;
            float bir = bi[c], biz = bi[8 + c], bin = bi[16 + c];
            float bhr = bh[c], bhz = bh[8 + c], bhn = bh[16 + c];
#pragma unroll
            for (int i = 0; i < 4; i++) {
                float r = sigf(red2(Ar[i]) + bir + red2(Br[i]) + bhr);
                float z = sigf(red2(Az[i]) + biz + red2(Bz[i]) + bhz);
                float n = tanhf(red2(An[i]) + bin + r * (red2(Bn[i]) + bhn));
                __stcg(&hdst[(rq + 32 * i) * CDIM + scol], (1.f - z) * n + z * hold[i]);
            }
            group_barrier(grp, (++bar_ep) * NSLICE);
        }

        // ========== output layer (slices 0..19: 2 cols x 128 rows) ==========
        if (s < 20) {
            int lr = tid >> 1;
            int c2 = tid & 1;
            ull A = 0ull;
            const float* wp = sm + O_WOW + c2 * PDK;
            Pre4 ph;
            ld4(ph, h3n, 0);
            st4(ph, xs);
            __syncthreads();
            for (int ch = 0; ch < 8; ch++) {
                if (ch < 7) ld4(ph, h3n, (ch + 1) * KCH);
                int k0 = ch * KCH;
#pragma unroll
                for (int k4 = 0; k4 < 8; k4++) {
                    F4U W; W.f = *reinterpret_cast<const float4*>(wp + k0 + k4 * 4);
                    F4U X; X.f = *reinterpret_cast<const float4*>(&xs[lr * XSTR + k4 * 4]);
                    fma2(A, W.u[0], X.u[0]);
                    fma2(A, W.u[1], X.u[1]);
                }
                __syncthreads();
                if (ch < 7) { st4(ph, xs); __syncthreads(); }
            }
            float v = tanhf(red2(A) + sm[O_OB + c2]);
            int Row = grow0 + lr;
            int oc = s * 2 + c2;
            out[(size_t)Row * ostride + st * SUBD + oc] = v;
            __stcg(&pvg[lr * SUBD + oc], v);
        }
        group_barrier(grp, (++bar_ep) * NSLICE);
    }
}

// ---------------- launcher ----------------
extern "C" void kernel_launch(void* const* d_in, const int* in_sizes, int n_in,
                              void* d_out, int out_size) {
    const float* feat   = (const float*)d_in[0];
    const float* fd1_w  = (const float*)d_in[1];
    const float* fd1_b  = (const float*)d_in[2];
    const float* c1_w   = (const float*)d_in[3];
    const float* c1_b   = (const float*)d_in[4];
    const float* c2_w   = (const float*)d_in[5];
    const float* c2_b   = (const float*)d_in[6];
    const float* fd2_w  = (const float*)d_in[7];
    const float* fd2_b  = (const float*)d_in[8];
    const float* d1_w   = (const float*)d_in[9];
    const float* d1_b   = (const float*)d_in[10];
    const float* d2_w   = (const float*)d_in[11];
    const float* d2_b   = (const float*)d_in[12];
    const float* g1_wih = (const float*)d_in[13];
    const float* g1_whh = (const float*)d_in[14];
    const float* g1_bih = (const float*)d_in[15];
    const float* g1_bhh = (const float*)d_in[16];
    const float* g2_wih = (const float*)d_in[17];
    const float* g2_whh = (const float*)d_in[18];
    const float* g2_bih = (const float*)d_in[19];
    const float* g2_bhh = (const float*)d_in[20];
    const float* g3_wih = (const float*)d_in[21];
    const float* g3_whh = (const float*)d_in[22];
    const float* g3_bih = (const float*)d_in[23];
    const float* g3_bhh = (const float*)d_in[24];
    const float* ow     = (const float*)d_in[25];
    const float* ob     = (const float*)d_in[26];
    const int*   nbf    = (const int*)d_in[27];
    float* out = (float*)d_out;

    float* pState;
    cudaGetSymbolAddress((void**)&pState, g_state);

    static bool attr_set = false;
    if (!attr_set) {
        cudaFuncSetAttribute(cond_fused, cudaFuncAttributeMaxDynamicSharedMemorySize,
                             56 * CPAD * 4);
        cudaFuncSetAttribute(ar_kernel, cudaFuncAttributeMaxDynamicSharedMemorySize, SM_BYTES);
        attr_set = true;
    }

    // launch 1: single memset for all AR state
    cudaMemsetAsync(pState, 0, STATE_TOT * sizeof(float));
    // launch 2: all weight transposes
    transpose_all<<<(TTOT + 255) / 256, 256>>>(fd1_w, c1_w, c2_w, fd2_w, d1_w);
    // launch 3: fd1
    fd1_kernel<<<BATCH * TFEAT, 256>>>(feat, fd1_b);
    // launch 4: fused conv1+conv2+fc+CP
    cond_fused<<<dim3(13, BATCH), 256, 56 * CPAD * 4>>>(c1_b, c2_b, fd2_b, d1_b);
    // launch 5: persistent AR decoder (ncu capture slot)
    ar_kernel<<<NCTA, NTHR, SM_BYTES>>>(
        d1_w, d2_w, d2_b,
        g1_wih, g1_whh, g1_bih, g1_bhh,
        g2_wih, g2_whh, g2_bih, g2_bhh,
        g3_wih, g3_whh, g3_bih, g3_bhh,
        ow, ob, nbf, out);
}